// round 1
// baseline (speedup 1.0000x reference)
#include <cuda_runtime.h>
#include <math.h>

// ---------------- problem constants ----------------
#define LTOT 2304      // IMG + TXT
#define IMGN 2048
#define TXTN 256
#define HIDN 3072
#define NH   24
#define DH   128
#define MLPN 12288
#define REFN 512
#define CATN (HIDN + MLPN)        // 15360
#define L1N  (3*HIDN + MLPN)      // 21504
#define HD   (NH*DH)              // 3072

// ---------------- device scratch (no cudaMalloc allowed) ----------------
__device__ float g_sv[HIDN];
__device__ float g_mod[3*HIDN];
__device__ float g_xmod[(size_t)LTOT*HIDN];
__device__ float g_lin1[(size_t)LTOT*L1N];
__device__ float g_q[(size_t)LTOT*HIDN];
__device__ float g_k[(size_t)LTOT*HIDN];
__device__ float g_v[(size_t)LTOT*HIDN];
__device__ float g_cat[(size_t)LTOT*CATN];
__device__ float g_refk[(size_t)REFN*HIDN];
__device__ float g_refv[(size_t)REFN*HIDN];
__device__ float g_outlin[(size_t)LTOT*HIDN];

// ---------------- small elementwise kernels ----------------
__global__ void silu_kernel(const float* __restrict__ v, float* __restrict__ sv) {
    int i = blockIdx.x*blockDim.x + threadIdx.x;
    if (i < HIDN) { float x = v[i]; sv[i] = x / (1.f + __expf(-x)); }
}

// mod = silu(vec) @ w_mod + b_mod   (1x3072 @ 3072x9216)
__global__ void modproj_kernel(const float* __restrict__ sv, const float* __restrict__ w,
                               const float* __restrict__ b, float* __restrict__ mod) {
    int n = blockIdx.x*blockDim.x + threadIdx.x;  // < 9216
    float acc = 0.f;
#pragma unroll 8
    for (int k = 0; k < HIDN; k++)
        acc = fmaf(sv[k], w[(size_t)k*(3*HIDN) + n], acc);
    mod[n] = acc + b[n];
}

// x_mod = layernorm(x) * (1+scl) + shift   (one block per row)
__global__ void ln_mod_kernel(const float* __restrict__ x, const float* __restrict__ mod,
                              float* __restrict__ xm) {
    int row = blockIdx.x;
    int tid = threadIdx.x;
    const float* xr = x + (size_t)row*HIDN;
    float s = 0.f, s2 = 0.f;
    for (int i = tid; i < HIDN; i += 256) { float v = xr[i]; s += v; s2 += v*v; }
    __shared__ float rs[256], rs2[256];
    rs[tid] = s; rs2[tid] = s2; __syncthreads();
    for (int o = 128; o > 0; o >>= 1) {
        if (tid < o) { rs[tid] += rs[tid+o]; rs2[tid] += rs2[tid+o]; }
        __syncthreads();
    }
    float mean = rs[0] * (1.f/HIDN);
    float var  = rs2[0] * (1.f/HIDN) - mean*mean;
    float inv  = rsqrtf(var + 1e-6f);
    float* xo = xm + (size_t)row*HIDN;
    for (int i = tid; i < HIDN; i += 256) {
        float v = (xr[i] - mean) * inv;
        xo[i] = v * (1.f + mod[HIDN + i]) + mod[i];
    }
}

// ---------------- SGEMM: C[M,N] = A[M,K] @ B[K,N] + bias  (M%128==0, N%128==0, K%8==0)
__launch_bounds__(256)
__global__ void sgemm_kernel(const float* __restrict__ A, const float* __restrict__ B,
                             const float* __restrict__ bias, float* __restrict__ C,
                             int M, int N, int K) {
    __shared__ float As[8][132];   // [k][m], padded
    __shared__ float Bs[8][132];   // [k][n], padded
    int tid = threadIdx.x;
    int tr = tid >> 4, tc = tid & 15;           // 16x16 thread grid
    int bm = blockIdx.y * 128, bn = blockIdx.x * 128;
    int a_row = tid >> 1, a_col = (tid & 1) * 4;
    int b_row = tid >> 5, b_col = (tid & 31) * 4;
    const float* Ap = A + (size_t)(bm + a_row)*K + a_col;
    const float* Bp = B + (size_t)b_row*N + bn + b_col;
    float acc[8][8];
#pragma unroll
    for (int i = 0; i < 8; i++)
#pragma unroll
        for (int j = 0; j < 8; j++) acc[i][j] = 0.f;

    for (int k0 = 0; k0 < K; k0 += 8) {
        float4 av = *(const float4*)(Ap + k0);
        As[a_col+0][a_row] = av.x; As[a_col+1][a_row] = av.y;
        As[a_col+2][a_row] = av.z; As[a_col+3][a_row] = av.w;
        float4 bv = *(const float4*)(Bp + (size_t)k0*N);
        *(float4*)&Bs[b_row][b_col] = bv;
        __syncthreads();
#pragma unroll
        for (int kk = 0; kk < 8; kk++) {
            float ar[8], br[8];
            *(float4*)&ar[0] = *(float4*)&As[kk][tr*8];
            *(float4*)&ar[4] = *(float4*)&As[kk][tr*8 + 4];
            *(float4*)&br[0] = *(float4*)&Bs[kk][tc*4];          // cols tc*4 .. +3
            *(float4*)&br[4] = *(float4*)&Bs[kk][64 + tc*4];     // cols 64+tc*4 ..
#pragma unroll
            for (int i = 0; i < 8; i++)
#pragma unroll
                for (int j = 0; j < 8; j++)
                    acc[i][j] = fmaf(ar[i], br[j], acc[i][j]);
        }
        __syncthreads();
    }
#pragma unroll
    for (int i = 0; i < 8; i++) {
        int row = bm + tr*8 + i;
        float* Cp = C + (size_t)row*N + bn;
#pragma unroll
        for (int j = 0; j < 4; j++) {
            int c0 = tc*4 + j, c1 = 64 + tc*4 + j;
            Cp[c0] = acc[i][j]   + bias[bn + c0];
            Cp[c1] = acc[i][j+4] + bias[bn + c1];
        }
    }
}

// ---------------- qkv split: rmsnorm q/k + rope on img tokens, scatter to [L,H,D]
__global__ void qkv_norm_rope_kernel(const float* __restrict__ lin1,
                                     const float* __restrict__ qn_w, const float* __restrict__ kn_w,
                                     const float* __restrict__ cosT, const float* __restrict__ sinT,
                                     float* __restrict__ qo, float* __restrict__ ko,
                                     float* __restrict__ vo) {
    int t = blockIdx.x, h = blockIdx.y, d = threadIdx.x;  // d in [0,128)
    const float* base = lin1 + (size_t)t*L1N + h*DH;
    float q = base[d];
    float k = base[HIDN + d];
    float v = base[2*HIDN + d];
    // block reduce sum of squares (128 threads = 4 warps)
    float s1 = q*q, s2 = k*k;
#pragma unroll
    for (int o = 16; o > 0; o >>= 1) {
        s1 += __shfl_down_sync(0xffffffffu, s1, o);
        s2 += __shfl_down_sync(0xffffffffu, s2, o);
    }
    __shared__ float red[8];
    int wid = d >> 5, lid = d & 31;
    if (lid == 0) { red[wid] = s1; red[4+wid] = s2; }
    __syncthreads();
    float qs = rsqrtf((red[0]+red[1]+red[2]+red[3]) * (1.f/DH) + 1e-6f);
    float ks = rsqrtf((red[4]+red[5]+red[6]+red[7]) * (1.f/DH) + 1e-6f);
    q = q * qs * qn_w[d];
    k = k * ks * kn_w[d];
    __shared__ float sq[DH], sk[DH];
    sq[d] = q; sk[d] = k;
    __syncthreads();
    if (t < IMGN) {
        int i = d >> 1;
        float c = cosT[t*(DH/2) + i], s = sinT[t*(DH/2) + i];
        float x1 = sq[2*i], x2 = sq[2*i+1];
        q = (d & 1) ? (x1*s + x2*c) : (x1*c - x2*s);
        x1 = sk[2*i]; x2 = sk[2*i+1];
        k = (d & 1) ? (x1*s + x2*c) : (x1*c - x2*s);
    }
    size_t o = ((size_t)t*NH + h)*DH + d;
    qo[o] = q; ko[o] = k; vo[o] = v;
}

// ref_k: rmsnorm + rope in place ([REF, H*D] layout, all rows roped)
__global__ void ref_norm_rope_kernel(float* __restrict__ rk, const float* __restrict__ w,
                                     const float* __restrict__ cosT, const float* __restrict__ sinT) {
    int t = blockIdx.x, h = blockIdx.y, d = threadIdx.x;
    float* base = rk + (size_t)t*HIDN + h*DH;
    float kv = base[d];
    float s = kv*kv;
#pragma unroll
    for (int o = 16; o > 0; o >>= 1) s += __shfl_down_sync(0xffffffffu, s, o);
    __shared__ float red[4];
    int wid = d >> 5, lid = d & 31;
    if (lid == 0) red[wid] = s;
    __syncthreads();
    float kn = kv * rsqrtf((red[0]+red[1]+red[2]+red[3]) * (1.f/DH) + 1e-6f) * w[d];
    __shared__ float sk[DH];
    sk[d] = kn;
    __syncthreads();
    int i = d >> 1;
    float c = cosT[t*(DH/2) + i], sn = sinT[t*(DH/2) + i];
    float x1 = sk[2*i], x2 = sk[2*i+1];
    base[d] = (d & 1) ? (x1*sn + x2*c) : (x1*c - x2*sn);
}

// gelu(mlp) into cat[:, 3072:]
__global__ void gelu_cat_kernel(const float* __restrict__ lin1, float* __restrict__ cat) {
    int idx = blockIdx.x*blockDim.x + threadIdx.x;  // < L*MLP
    int t = idx / MLPN, j = idx - t*MLPN;
    float x = lin1[(size_t)t*L1N + 3*HIDN + j];
    float g = 0.5f*x*(1.f + tanhf(0.7978845608028654f*(x + 0.044715f*x*x*x)));
    cat[(size_t)t*CATN + HIDN + j] = g;
}

// ---------------- flash attention (fp32, 64x64 tiles, 256 threads) ----------------
// Q,K,V: [L, H*D] contiguous. O row stride = out_stride, head offset h*128.
#define FA_QS 0
#define FA_KS (64*132)
#define FA_VS (FA_KS + 64*132)
#define FA_SS (FA_VS + 64*128)
#define FA_M  (FA_SS + 64*65)
#define FA_L  (FA_M + 64)
#define FA_A  (FA_L + 64)
#define FA_SMEM_FLOATS (FA_A + 64)
#define FA_SMEM_BYTES (FA_SMEM_FLOATS*4)

__launch_bounds__(256)
__global__ void flash_attn_kernel(const float* __restrict__ Q, const float* __restrict__ K,
                                  const float* __restrict__ V, float* __restrict__ O,
                                  int Lk, int out_stride, int accumulate) {
    extern __shared__ float sm[];
    float* Qs = sm + FA_QS;     // stride 132
    float* Ks = sm + FA_KS;     // stride 132
    float* Vs = sm + FA_VS;     // stride 128
    float* Ss = sm + FA_SS;     // stride 65
    float* mrow = sm + FA_M;
    float* lrow = sm + FA_L;
    float* arow = sm + FA_A;

    int tid = threadIdx.x;
    int h = blockIdx.y;
    int q0 = blockIdx.x * 64;
    int tr = tid >> 4, tc = tid & 15;
    const float scale = 0.08838834764831845f;  // 1/sqrt(128)

    // load Q tile
#pragma unroll
    for (int u = 0; u < 8; u++) {
        int idx = u*256 + tid;
        int r = idx >> 5; int d4 = (idx & 31) * 4;
        *(float4*)&Qs[r*132 + d4] = *(const float4*)&Q[(size_t)(q0+r)*HD + h*DH + d4];
    }
    if (tid < 64) { mrow[tid] = -1e30f; lrow[tid] = 0.f; }
    float acc[4][8];
#pragma unroll
    for (int i = 0; i < 4; i++)
#pragma unroll
        for (int j = 0; j < 8; j++) acc[i][j] = 0.f;
    __syncthreads();

    for (int k0 = 0; k0 < Lk; k0 += 64) {
#pragma unroll
        for (int u = 0; u < 8; u++) {
            int idx = u*256 + tid;
            int r = idx >> 5; int d4 = (idx & 31) * 4;
            *(float4*)&Ks[r*132 + d4] = *(const float4*)&K[(size_t)(k0+r)*HD + h*DH + d4];
            *(float4*)&Vs[r*128 + d4] = *(const float4*)&V[(size_t)(k0+r)*HD + h*DH + d4];
        }
        __syncthreads();

        // S = scale * Q K^T ; thread owns rows tr+16i, cols tc+16j
        float s4[4][4];
#pragma unroll
        for (int i = 0; i < 4; i++)
#pragma unroll
            for (int j = 0; j < 4; j++) s4[i][j] = 0.f;
        for (int d = 0; d < 128; d += 4) {
            float a[4][4], b[4][4];
#pragma unroll
            for (int i = 0; i < 4; i++) *(float4*)a[i] = *(float4*)&Qs[(tr+16*i)*132 + d];
#pragma unroll
            for (int j = 0; j < 4; j++) *(float4*)b[j] = *(float4*)&Ks[(tc+16*j)*132 + d];
#pragma unroll
            for (int i = 0; i < 4; i++)
#pragma unroll
                for (int j = 0; j < 4; j++) {
                    s4[i][j] = fmaf(a[i][0], b[j][0], s4[i][j]);
                    s4[i][j] = fmaf(a[i][1], b[j][1], s4[i][j]);
                    s4[i][j] = fmaf(a[i][2], b[j][2], s4[i][j]);
                    s4[i][j] = fmaf(a[i][3], b[j][3], s4[i][j]);
                }
        }
#pragma unroll
        for (int i = 0; i < 4; i++)
#pragma unroll
            for (int j = 0; j < 4; j++)
                Ss[(tr+16*i)*65 + tc+16*j] = s4[i][j]*scale;
        __syncthreads();

        // online softmax: one row per thread (threads 0..63)
        if (tid < 64) {
            float m_old = mrow[tid];
            float m = m_old;
            for (int c = 0; c < 64; c++) m = fmaxf(m, Ss[tid*65 + c]);
            float alpha = __expf(m_old - m);
            float sum = 0.f;
            for (int c = 0; c < 64; c++) {
                float p = __expf(Ss[tid*65 + c] - m);
                Ss[tid*65 + c] = p;
                sum += p;
            }
            mrow[tid] = m;
            lrow[tid] = lrow[tid]*alpha + sum;
            arow[tid] = alpha;
        }
        __syncthreads();

        // rescale acc and accumulate P @ V ; thread cols: tc*4+j and 64+tc*4+j
        float al[4];
#pragma unroll
        for (int i = 0; i < 4; i++) al[i] = arow[tr + 16*i];
#pragma unroll
        for (int i = 0; i < 4; i++)
#pragma unroll
            for (int j = 0; j < 8; j++) acc[i][j] *= al[i];
        for (int kk = 0; kk < 64; kk++) {
            float p[4];
#pragma unroll
            for (int i = 0; i < 4; i++) p[i] = Ss[(tr+16*i)*65 + kk];
            float4 v0 = *(float4*)&Vs[kk*128 + tc*4];
            float4 v1 = *(float4*)&Vs[kk*128 + 64 + tc*4];
#pragma unroll
            for (int i = 0; i < 4; i++) {
                acc[i][0] = fmaf(p[i], v0.x, acc[i][0]);
                acc[i][1] = fmaf(p[i], v0.y, acc[i][1]);
                acc[i][2] = fmaf(p[i], v0.z, acc[i][2]);
                acc[i][3] = fmaf(p[i], v0.w, acc[i][3]);
                acc[i][4] = fmaf(p[i], v1.x, acc[i][4]);
                acc[i][5] = fmaf(p[i], v1.y, acc[i][5]);
                acc[i][6] = fmaf(p[i], v1.z, acc[i][6]);
                acc[i][7] = fmaf(p[i], v1.w, acc[i][7]);
            }
        }
        __syncthreads();
    }
#pragma unroll
    for (int i = 0; i < 4; i++) {
        int r = tr + 16*i;
        float invl = 1.f / lrow[r];
        float* op = O + (size_t)(q0 + r)*out_stride + h*DH;
#pragma unroll
        for (int j = 0; j < 4; j++) {
            int c0 = tc*4 + j, c1 = 64 + tc*4 + j;
            float v0a = acc[i][j]  * invl;
            float v1a = acc[i][j+4]* invl;
            if (accumulate) { op[c0] += v0a; op[c1] += v1a; }
            else            { op[c0] = v0a;  op[c1] = v1a; }
        }
    }
}

// out = x + gate * outlin
__global__ void final_kernel(const float* __restrict__ x, const float* __restrict__ mod,
                             const float* __restrict__ outlin, float* __restrict__ out) {
    int idx = blockIdx.x*blockDim.x + threadIdx.x;  // < L*HID
    int col = idx % HIDN;
    out[idx] = x[idx] + mod[2*HIDN + col]*outlin[idx];
}

// ---------------- launcher ----------------
extern "C" void kernel_launch(void* const* d_in, const int* in_sizes, int n_in,
                              void* d_out, int out_size) {
    const float* x          = (const float*)d_in[0];
    const float* vec        = (const float*)d_in[1];
    const float* cosT       = (const float*)d_in[2];
    const float* sinT       = (const float*)d_in[3];
    const float* ref_latent = (const float*)d_in[4];
    const float* ref_cos    = (const float*)d_in[5];
    const float* ref_sin    = (const float*)d_in[6];
    const float* w_mod      = (const float*)d_in[7];
    const float* b_mod      = (const float*)d_in[8];
    const float* w1         = (const float*)d_in[9];
    const float* b1         = (const float*)d_in[10];
    const float* w2         = (const float*)d_in[11];
    const float* b2         = (const float*)d_in[12];
    const float* qn_w       = (const float*)d_in[13];
    const float* kn_w       = (const float*)d_in[14];
    const float* wk_ip      = (const float*)d_in[15];
    const float* bk_ip      = (const float*)d_in[16];
    const float* wv_ip      = (const float*)d_in[17];
    const float* bv_ip      = (const float*)d_in[18];
    const float* ref_kn_w   = (const float*)d_in[19];
    float* out = (float*)d_out;

    float *sv, *modb, *xmod, *lin1, *qb, *kb, *vb, *cat, *refk, *refv, *outlin;
    cudaGetSymbolAddress((void**)&sv,     g_sv);
    cudaGetSymbolAddress((void**)&modb,   g_mod);
    cudaGetSymbolAddress((void**)&xmod,   g_xmod);
    cudaGetSymbolAddress((void**)&lin1,   g_lin1);
    cudaGetSymbolAddress((void**)&qb,     g_q);
    cudaGetSymbolAddress((void**)&kb,     g_k);
    cudaGetSymbolAddress((void**)&vb,     g_v);
    cudaGetSymbolAddress((void**)&cat,    g_cat);
    cudaGetSymbolAddress((void**)&refk,   g_refk);
    cudaGetSymbolAddress((void**)&refv,   g_refv);
    cudaGetSymbolAddress((void**)&outlin, g_outlin);

    cudaFuncSetAttribute(flash_attn_kernel,
                         cudaFuncAttributeMaxDynamicSharedMemorySize, FA_SMEM_BYTES);

    // 1. mod = silu(vec) @ w_mod + b_mod
    silu_kernel<<<12, 256>>>(vec, sv);
    modproj_kernel<<<36, 256>>>(sv, w_mod, b_mod, modb);

    // 2. layernorm + modulate
    ln_mod_kernel<<<LTOT, 256>>>(x, modb, xmod);

    // 3. lin1 = x_mod @ w1 + b1  (2304 x 21504 x 3072)
    sgemm_kernel<<<dim3(L1N/128, LTOT/128), 256>>>(xmod, w1, b1, lin1, LTOT, L1N, HIDN);

    // 4. qkv: rmsnorm + rope ; gelu(mlp) into cat
    qkv_norm_rope_kernel<<<dim3(LTOT, NH), 128>>>(lin1, qn_w, kn_w, cosT, sinT, qb, kb, vb);
    gelu_cat_kernel<<<(LTOT*MLPN)/256, 256>>>(lin1, cat);

    // 5. ref K/V projections + rmsnorm + rope (v needs no processing; layout matches)
    sgemm_kernel<<<dim3(HIDN/128, REFN/128), 256>>>(ref_latent, wk_ip, bk_ip, refk, REFN, HIDN, HIDN);
    sgemm_kernel<<<dim3(HIDN/128, REFN/128), 256>>>(ref_latent, wv_ip, bv_ip, refv, REFN, HIDN, HIDN);
    ref_norm_rope_kernel<<<dim3(REFN, NH), 128>>>(refk, ref_kn_w, ref_cos, ref_sin);

    // 6. attention: self-attn into cat[:, :3072], then IP attention accumulated
    flash_attn_kernel<<<dim3(LTOT/64, NH), 256, FA_SMEM_BYTES>>>(qb, kb, vb, cat, LTOT, CATN, 0);
    flash_attn_kernel<<<dim3(LTOT/64, NH), 256, FA_SMEM_BYTES>>>(qb, refk, refv, cat, REFN, CATN, 1);

    // 7. out = cat @ w2 + b2  (2304 x 3072 x 15360)
    sgemm_kernel<<<dim3(HIDN/128, LTOT/128), 256>>>(cat, w2, b2, outlin, LTOT, HIDN, CATN);

    // 8. residual: x + gate * out
    final_kernel<<<(LTOT*HIDN)/256, 256>>>(x, modb, outlin, out);
}

// round 3
// speedup vs baseline: 2.3938x; 2.3938x over previous
#include <cuda_runtime.h>
#include <cuda_bf16.h>
#include <cstdint>
#include <math.h>

// ---------------- problem constants ----------------
#define LTOT 2304      // IMG + TXT
#define IMGN 2048
#define TXTN 256
#define HIDN 3072
#define NH   24
#define DH   128
#define MLPN 12288
#define REFN 512
#define CATN (HIDN + MLPN)        // 15360
#define L1N  (3*HIDN + MLPN)      // 21504
#define HD   (NH*DH)              // 3072

// ---------------- helpers ----------------
__device__ __forceinline__ uint32_t smem_u32(const void* p) {
    uint32_t a;
    asm("{ .reg .u64 t; cvta.to.shared.u64 t, %1; cvt.u32.u64 %0, t; }" : "=r"(a) : "l"(p));
    return a;
}
#define SMEM_SWIZZLE_128B(byte_offset) ((byte_offset) ^ (((byte_offset) >> 3) & 0x70))

__device__ __forceinline__ void cp16(uint32_t saddr, const void* g) {
    asm volatile("cp.async.cg.shared.global [%0], [%1], 16;" :: "r"(saddr), "l"(g));
}
#define CP_COMMIT() asm volatile("cp.async.commit_group;" ::: "memory")
#define CP_WAIT1()  asm volatile("cp.async.wait_group 1;" ::: "memory")
#define CP_WAIT0()  asm volatile("cp.async.wait_group 0;" ::: "memory")

__device__ __forceinline__ void ldsm4(uint32_t r[4], uint32_t addr) {
    asm volatile("ldmatrix.sync.aligned.m8n8.x4.shared.b16 {%0,%1,%2,%3}, [%4];"
        : "=r"(r[0]), "=r"(r[1]), "=r"(r[2]), "=r"(r[3]) : "r"(addr));
}
__device__ __forceinline__ void ldsm2(uint32_t r[2], uint32_t addr) {
    asm volatile("ldmatrix.sync.aligned.m8n8.x2.shared.b16 {%0,%1}, [%2];"
        : "=r"(r[0]), "=r"(r[1]) : "r"(addr));
}
__device__ __forceinline__ void mma16816(float c[4], const uint32_t a[4], const uint32_t b[2]) {
    asm volatile("mma.sync.aligned.m16n8k16.row.col.f32.bf16.bf16.f32 "
        "{%0,%1,%2,%3}, {%4,%5,%6,%7}, {%8,%9}, {%0,%1,%2,%3};"
        : "+f"(c[0]), "+f"(c[1]), "+f"(c[2]), "+f"(c[3])
        : "r"(a[0]), "r"(a[1]), "r"(a[2]), "r"(a[3]), "r"(b[0]), "r"(b[1]));
}

__device__ __forceinline__ void split2(float x, __nv_bfloat16& h, __nv_bfloat16& l) {
    h = __float2bfloat16(x);
    l = __float2bfloat16(x - __bfloat162float(h));
}

// ---------------- device scratch ----------------
__device__ float g_sv[HIDN];
__device__ float g_mod[3*HIDN];
__device__ __nv_bfloat16 g_xh[(size_t)LTOT*HIDN];
__device__ __nv_bfloat16 g_xl[(size_t)LTOT*HIDN];
__device__ float g_lin1[(size_t)LTOT*L1N];
__device__ float g_q[(size_t)LTOT*HIDN];
__device__ float g_k[(size_t)LTOT*HIDN];
__device__ float g_v[(size_t)LTOT*HIDN];
__device__ float g_attn[(size_t)LTOT*HIDN];
__device__ __nv_bfloat16 g_cath[(size_t)LTOT*CATN];
__device__ __nv_bfloat16 g_catl[(size_t)LTOT*CATN];
__device__ float g_refk[(size_t)REFN*HIDN];
__device__ float g_refv[(size_t)REFN*HIDN];
__device__ __nv_bfloat16 g_rlh[(size_t)REFN*HIDN];
__device__ __nv_bfloat16 g_rll[(size_t)REFN*HIDN];
__device__ float g_outlin[(size_t)LTOT*HIDN];
__device__ __nv_bfloat16 g_w1h[(size_t)L1N*HIDN];
__device__ __nv_bfloat16 g_w1l[(size_t)L1N*HIDN];
__device__ __nv_bfloat16 g_w2h[(size_t)HIDN*CATN];
__device__ __nv_bfloat16 g_w2l[(size_t)HIDN*CATN];
__device__ __nv_bfloat16 g_wkh[(size_t)HIDN*HIDN];
__device__ __nv_bfloat16 g_wkl[(size_t)HIDN*HIDN];
__device__ __nv_bfloat16 g_wvh[(size_t)HIDN*HIDN];
__device__ __nv_bfloat16 g_wvl[(size_t)HIDN*HIDN];

// ---------------- small kernels ----------------
__global__ void silu_kernel(const float* __restrict__ v, float* __restrict__ sv) {
    int i = blockIdx.x*blockDim.x + threadIdx.x;
    if (i < HIDN) { float x = v[i]; sv[i] = x / (1.f + __expf(-x)); }
}

__global__ void modproj_kernel(const float* __restrict__ sv, const float* __restrict__ w,
                               const float* __restrict__ b, float* __restrict__ mod) {
    int n = blockIdx.x*blockDim.x + threadIdx.x;  // < 9216
    float acc = 0.f;
#pragma unroll 8
    for (int k = 0; k < HIDN; k++)
        acc = fmaf(sv[k], w[(size_t)k*(3*HIDN) + n], acc);
    mod[n] = acc + b[n];
}

// layernorm + modulate, write split bf16
__global__ void ln_mod_kernel(const float* __restrict__ x, const float* __restrict__ mod,
                              __nv_bfloat16* __restrict__ xh, __nv_bfloat16* __restrict__ xl) {
    int row = blockIdx.x;
    int tid = threadIdx.x;
    const float* xr = x + (size_t)row*HIDN;
    float s = 0.f, s2 = 0.f;
    for (int i = tid; i < HIDN; i += 256) { float v = xr[i]; s += v; s2 += v*v; }
    __shared__ float rs[256], rs2[256];
    rs[tid] = s; rs2[tid] = s2; __syncthreads();
    for (int o = 128; o > 0; o >>= 1) {
        if (tid < o) { rs[tid] += rs[tid+o]; rs2[tid] += rs2[tid+o]; }
        __syncthreads();
    }
    float mean = rs[0] * (1.f/HIDN);
    float var  = rs2[0] * (1.f/HIDN) - mean*mean;
    float inv  = rsqrtf(var + 1e-6f);
    for (int i = tid; i < HIDN; i += 256) {
        float v = (xr[i] - mean) * inv;
        v = v * (1.f + mod[HIDN + i]) + mod[i];
        __nv_bfloat16 h, l; split2(v, h, l);
        xh[(size_t)row*HIDN + i] = h;
        xl[(size_t)row*HIDN + i] = l;
    }
}

// transpose + split: w[K,N] fp32 -> hi/lo[N,K] bf16
__global__ void wsplitT_kernel(const float* __restrict__ w,
                               __nv_bfloat16* __restrict__ hi, __nv_bfloat16* __restrict__ lo,
                               int K, int N) {
    __shared__ float t[32][33];
    int n0 = blockIdx.x*32, k0 = blockIdx.y*32;
    int tx = threadIdx.x, ty = threadIdx.y;  // 32 x 8
#pragma unroll
    for (int i = 0; i < 32; i += 8)
        t[ty+i][tx] = w[(size_t)(k0+ty+i)*N + n0+tx];
    __syncthreads();
#pragma unroll
    for (int i = 0; i < 32; i += 8) {
        float v = t[tx][ty+i];
        __nv_bfloat16 h, l; split2(v, h, l);
        size_t o = (size_t)(n0+ty+i)*K + k0+tx;
        hi[o] = h; lo[o] = l;
    }
}

__global__ void split_kernel(const float* __restrict__ src,
                             __nv_bfloat16* __restrict__ hi, __nv_bfloat16* __restrict__ lo,
                             size_t n) {
    size_t i = (size_t)blockIdx.x*blockDim.x + threadIdx.x;
    if (i < n) {
        __nv_bfloat16 h, l; split2(src[i], h, l);
        hi[i] = h; lo[i] = l;
    }
}

// ---------------- HMMA split-bf16 GEMM ----------------
// C[M,N] = (Ahi+Alo)[M,K] @ (Bhi+Blo)[N,K]^T + bias
// CTA tile 128x128, K-chunk 64, 8 warps (each 64x32), double-buffered cp.async.
// SMEM stage: Ahi 16K | Alo 16K | Bhi 16K | Blo 16K = 64K; 2 stages = 128K.
#define GS_A   0
#define GS_AL  16384
#define GS_B   32768
#define GS_BL  49152
#define GS_STAGE 65536
#define GK_SMEM_TOTAL (2*GS_STAGE)

__global__ void __launch_bounds__(256, 1) tc_gemm_kernel(
    const __nv_bfloat16* __restrict__ Ahi, const __nv_bfloat16* __restrict__ Alo,
    const __nv_bfloat16* __restrict__ Bhi, const __nv_bfloat16* __restrict__ Blo,
    const float* __restrict__ bias, float* __restrict__ C,
    int M, int N, int K, int m_tiles)
{
    extern __shared__ char smem[];
    uint32_t sb = smem_u32(smem);
    int tid = threadIdx.x;
    int lane = tid & 31, wid = tid >> 5;
    int wm = wid >> 2, wn = wid & 3;   // warp tile: rows wm*64, cols wn*32

    int mi = blockIdx.x % m_tiles;
    int ni = blockIdx.x / m_tiles;
    int bm = mi * 128, bn = ni * 128;

    float acc[4][4][4];
#pragma unroll
    for (int i = 0; i < 4; i++)
#pragma unroll
        for (int j = 0; j < 4; j++)
#pragma unroll
            for (int r = 0; r < 4; r++) acc[i][j][r] = 0.f;

    // per-thread load mapping: 128 rows x 8 chunks(16B) per tile, 4 iters of 256 thr
    int lr = tid >> 1;                 // row contribution per iter: r = q*32? (see below)
    (void)lr;

    int NC = K >> 6;

    // ---- stage loader ----
    auto load_stage = [&](int st, int k0) {
        uint32_t base = sb + st*GS_STAGE;
#pragma unroll
        for (int q = 0; q < 4; q++) {
            int idx = q*256 + tid;
            int r = idx >> 3;
            int ch = (idx & 7) << 4;       // byte offset within 128B row
            uint32_t sw = SMEM_SWIZZLE_128B((uint32_t)(r*128 + ch));
            const char* pah = (const char*)(Ahi + (size_t)(bm + r)*K + k0) + ch;
            const char* pal = (const char*)(Alo + (size_t)(bm + r)*K + k0) + ch;
            const char* pbh = (const char*)(Bhi + (size_t)(bn + r)*K + k0) + ch;
            const char* pbl = (const char*)(Blo + (size_t)(bn + r)*K + k0) + ch;
            cp16(base + GS_A  + sw, pah);
            cp16(base + GS_AL + sw, pal);
            cp16(base + GS_B  + sw, pbh);
            cp16(base + GS_BL + sw, pbl);
        }
    };

    load_stage(0, 0);
    CP_COMMIT();

    for (int c = 0; c < NC; c++) {
        if (c + 1 < NC) { load_stage((c+1) & 1, (c+1) << 6); CP_COMMIT(); CP_WAIT1(); }
        else            { CP_WAIT0(); }
        __syncthreads();

        uint32_t base = sb + (c & 1)*GS_STAGE;
#pragma unroll
        for (int kk = 0; kk < 4; kk++) {
            uint32_t ah[4][4], al[4][4], bh[4][2], bl[4][2];
            int acol = kk*32 + ((lane >> 4) << 4);
            int arow = wm*64 + (lane & 15);
#pragma unroll
            for (int i = 0; i < 4; i++) {
                uint32_t sw = SMEM_SWIZZLE_128B((uint32_t)((arow + i*16)*128 + acol));
                ldsm4(ah[i], base + GS_A  + sw);
                ldsm4(al[i], base + GS_AL + sw);
            }
            int bcol = kk*32 + (((lane >> 3) & 1) << 4);
            int brow = wn*32 + (lane & 7);
#pragma unroll
            for (int j = 0; j < 4; j++) {
                uint32_t sw = SMEM_SWIZZLE_128B((uint32_t)((brow + j*8)*128 + bcol));
                ldsm2(bh[j], base + GS_B  + sw);
                ldsm2(bl[j], base + GS_BL + sw);
            }
#pragma unroll
            for (int i = 0; i < 4; i++)
#pragma unroll
                for (int j = 0; j < 4; j++) {
                    mma16816(acc[i][j], ah[i], bh[j]);
                    mma16816(acc[i][j], ah[i], bl[j]);
                    mma16816(acc[i][j], al[i], bh[j]);
                }
        }
        __syncthreads();
    }

    // ---- epilogue: direct global write + bias ----
#pragma unroll
    for (int i = 0; i < 4; i++) {
        int m0 = bm + wm*64 + i*16 + (lane >> 2);
#pragma unroll
        for (int j = 0; j < 4; j++) {
            int n = bn + wn*32 + j*8 + (lane & 3)*2;
            float b0 = bias[n], b1 = bias[n+1];
            float* c0 = C + (size_t)m0*N + n;
            c0[0] = acc[i][j][0] + b0;
            c0[1] = acc[i][j][1] + b1;
            float* c1 = C + (size_t)(m0+8)*N + n;
            c1[0] = acc[i][j][2] + b0;
            c1[1] = acc[i][j][3] + b1;
        }
    }
}

// ---------------- qkv split: rmsnorm q/k + rope ----------------
__global__ void qkv_norm_rope_kernel(const float* __restrict__ lin1,
                                     const float* __restrict__ qn_w, const float* __restrict__ kn_w,
                                     const float* __restrict__ cosT, const float* __restrict__ sinT,
                                     float* __restrict__ qo, float* __restrict__ ko,
                                     float* __restrict__ vo) {
    int t = blockIdx.x, h = blockIdx.y, d = threadIdx.x;
    const float* base = lin1 + (size_t)t*L1N + h*DH;
    float q = base[d];
    float k = base[HIDN + d];
    float v = base[2*HIDN + d];
    float s1 = q*q, s2 = k*k;
#pragma unroll
    for (int o = 16; o > 0; o >>= 1) {
        s1 += __shfl_down_sync(0xffffffffu, s1, o);
        s2 += __shfl_down_sync(0xffffffffu, s2, o);
    }
    __shared__ float red[8];
    int wid = d >> 5, lid = d & 31;
    if (lid == 0) { red[wid] = s1; red[4+wid] = s2; }
    __syncthreads();
    float qs = rsqrtf((red[0]+red[1]+red[2]+red[3]) * (1.f/DH) + 1e-6f);
    float ks = rsqrtf((red[4]+red[5]+red[6]+red[7]) * (1.f/DH) + 1e-6f);
    q = q * qs * qn_w[d];
    k = k * ks * kn_w[d];
    __shared__ float sq[DH], sk[DH];
    sq[d] = q; sk[d] = k;
    __syncthreads();
    if (t < IMGN) {
        int i = d >> 1;
        float c = cosT[t*(DH/2) + i], s = sinT[t*(DH/2) + i];
        float x1 = sq[2*i], x2 = sq[2*i+1];
        q = (d & 1) ? (x1*s + x2*c) : (x1*c - x2*s);
        x1 = sk[2*i]; x2 = sk[2*i+1];
        k = (d & 1) ? (x1*s + x2*c) : (x1*c - x2*s);
    }
    size_t o = ((size_t)t*NH + h)*DH + d;
    qo[o] = q; ko[o] = k; vo[o] = v;
}

__global__ void ref_norm_rope_kernel(float* __restrict__ rk, const float* __restrict__ w,
                                     const float* __restrict__ cosT, const float* __restrict__ sinT) {
    int t = blockIdx.x, h = blockIdx.y, d = threadIdx.x;
    float* base = rk + (size_t)t*HIDN + h*DH;
    float kv = base[d];
    float s = kv*kv;
#pragma unroll
    for (int o = 16; o > 0; o >>= 1) s += __shfl_down_sync(0xffffffffu, s, o);
    __shared__ float red[4];
    int wid = d >> 5, lid = d & 31;
    if (lid == 0) red[wid] = s;
    __syncthreads();
    float kn = kv * rsqrtf((red[0]+red[1]+red[2]+red[3]) * (1.f/DH) + 1e-6f) * w[d];
    __shared__ float sk[DH];
    sk[d] = kn;
    __syncthreads();
    int i = d >> 1;
    float c = cosT[t*(DH/2) + i], sn = sinT[t*(DH/2) + i];
    float x1 = sk[2*i], x2 = sk[2*i+1];
    base[d] = (d & 1) ? (x1*sn + x2*c) : (x1*c - x2*sn);
}

// gelu(mlp) -> cat hi/lo at col offset HIDN
__global__ void gelu_cat_kernel(const float* __restrict__ lin1,
                                __nv_bfloat16* __restrict__ ch, __nv_bfloat16* __restrict__ cl) {
    int idx = blockIdx.x*blockDim.x + threadIdx.x;
    int t = idx / MLPN, j = idx - t*MLPN;
    float x = lin1[(size_t)t*L1N + 3*HIDN + j];
    float g = 0.5f*x*(1.f + tanhf(0.7978845608028654f*(x + 0.044715f*x*x*x)));
    __nv_bfloat16 h, l; split2(g, h, l);
    size_t o = (size_t)t*CATN + HIDN + j;
    ch[o] = h; cl[o] = l;
}

// attn fp32 -> cat hi/lo at cols [0, HIDN)
__global__ void attn_cat_kernel(const float* __restrict__ attn,
                                __nv_bfloat16* __restrict__ ch, __nv_bfloat16* __restrict__ cl) {
    int idx = blockIdx.x*blockDim.x + threadIdx.x;
    int t = idx / HIDN, j = idx - t*HIDN;
    __nv_bfloat16 h, l; split2(attn[idx], h, l);
    size_t o = (size_t)t*CATN + j;
    ch[o] = h; cl[o] = l;
}

// ---------------- flash attention (fp32) ----------------
#define FA_QS 0
#define FA_KS (64*132)
#define FA_VS (FA_KS + 64*132)
#define FA_SS (FA_VS + 64*128)
#define FA_M  (FA_SS + 64*65)
#define FA_L  (FA_M + 64)
#define FA_A  (FA_L + 64)
#define FA_SMEM_FLOATS (FA_A + 64)
#define FA_SMEM_BYTES (FA_SMEM_FLOATS*4)

__launch_bounds__(256)
__global__ void flash_attn_kernel(const float* __restrict__ Q, const float* __restrict__ K,
                                  const float* __restrict__ V, float* __restrict__ O,
                                  int Lk, int out_stride, int accumulate) {
    extern __shared__ float sm[];
    float* Qs = sm + FA_QS;
    float* Ks = sm + FA_KS;
    float* Vs = sm + FA_VS;
    float* Ss = sm + FA_SS;
    float* mrow = sm + FA_M;
    float* lrow = sm + FA_L;
    float* arow = sm + FA_A;

    int tid = threadIdx.x;
    int h = blockIdx.y;
    int q0 = blockIdx.x * 64;
    int tr = tid >> 4, tc = tid & 15;
    const float scale = 0.08838834764831845f;

#pragma unroll
    for (int u = 0; u < 8; u++) {
        int idx = u*256 + tid;
        int r = idx >> 5; int d4 = (idx & 31) * 4;
        *(float4*)&Qs[r*132 + d4] = *(const float4*)&Q[(size_t)(q0+r)*HD + h*DH + d4];
    }
    if (tid < 64) { mrow[tid] = -1e30f; lrow[tid] = 0.f; }
    float acc[4][8];
#pragma unroll
    for (int i = 0; i < 4; i++)
#pragma unroll
        for (int j = 0; j < 8; j++) acc[i][j] = 0.f;
    __syncthreads();

    for (int k0 = 0; k0 < Lk; k0 += 64) {
#pragma unroll
        for (int u = 0; u < 8; u++) {
            int idx = u*256 + tid;
            int r = idx >> 5; int d4 = (idx & 31) * 4;
            *(float4*)&Ks[r*132 + d4] = *(const float4*)&K[(size_t)(k0+r)*HD + h*DH + d4];
            *(float4*)&Vs[r*128 + d4] = *(const float4*)&V[(size_t)(k0+r)*HD + h*DH + d4];
        }
        __syncthreads();

        float s4[4][4];
#pragma unroll
        for (int i = 0; i < 4; i++)
#pragma unroll
            for (int j = 0; j < 4; j++) s4[i][j] = 0.f;
        for (int d = 0; d < 128; d += 4) {
            float a[4][4], b[4][4];
#pragma unroll
            for (int i = 0; i < 4; i++) *(float4*)a[i] = *(float4*)&Qs[(tr+16*i)*132 + d];
#pragma unroll
            for (int j = 0; j < 4; j++) *(float4*)b[j] = *(float4*)&Ks[(tc+16*j)*132 + d];
#pragma unroll
            for (int i = 0; i < 4; i++)
#pragma unroll
                for (int j = 0; j < 4; j++) {
                    s4[i][j] = fmaf(a[i][0], b[j][0], s4[i][j]);
                    s4[i][j] = fmaf(a[i][1], b[j][1], s4[i][j]);
                    s4[i][j] = fmaf(a[i][2], b[j][2], s4[i][j]);
                    s4[i][j] = fmaf(a[i][3], b[j][3], s4[i][j]);
                }
        }
#pragma unroll
        for (int i = 0; i < 4; i++)
#pragma unroll
            for (int j = 0; j < 4; j++)
                Ss[(tr+16*i)*65 + tc+16*j] = s4[i][j]*scale;
        __syncthreads();

        if (tid < 64) {
            float m_old = mrow[tid];
            float m = m_old;
            for (int c = 0; c < 64; c++) m = fmaxf(m, Ss[tid*65 + c]);
            float alpha = __expf(m_old - m);
            float sum = 0.f;
            for (int c = 0; c < 64; c++) {
                float p = __expf(Ss[tid*65 + c] - m);
                Ss[tid*65 + c] = p;
                sum += p;
            }
            mrow[tid] = m;
            lrow[tid] = lrow[tid]*alpha + sum;
            arow[tid] = alpha;
        }
        __syncthreads();

        float al[4];
#pragma unroll
        for (int i = 0; i < 4; i++) al[i] = arow[tr + 16*i];
#pragma unroll
        for (int i = 0; i < 4; i++)
#pragma unroll
            for (int j = 0; j < 8; j++) acc[i][j] *= al[i];
        for (int kk = 0; kk < 64; kk++) {
            float p[4];
#pragma unroll
            for (int i = 0; i < 4; i++) p[i] = Ss[(tr+16*i)*65 + kk];
            float4 v0 = *(float4*)&Vs[kk*128 + tc*4];
            float4 v1 = *(float4*)&Vs[kk*128 + 64 + tc*4];
#pragma unroll
            for (int i = 0; i < 4; i++) {
                acc[i][0] = fmaf(p[i], v0.x, acc[i][0]);
                acc[i][1] = fmaf(p[i], v0.y, acc[i][1]);
                acc[i][2] = fmaf(p[i], v0.z, acc[i][2]);
                acc[i][3] = fmaf(p[i], v0.w, acc[i][3]);
                acc[i][4] = fmaf(p[i], v1.x, acc[i][4]);
                acc[i][5] = fmaf(p[i], v1.y, acc[i][5]);
                acc[i][6] = fmaf(p[i], v1.z, acc[i][6]);
                acc[i][7] = fmaf(p[i], v1.w, acc[i][7]);
            }
        }
        __syncthreads();
    }
#pragma unroll
    for (int i = 0; i < 4; i++) {
        int r = tr + 16*i;
        float invl = 1.f / lrow[r];
        float* op = O + (size_t)(q0 + r)*out_stride + h*DH;
#pragma unroll
        for (int j = 0; j < 4; j++) {
            int c0 = tc*4 + j, c1 = 64 + tc*4 + j;
            float v0a = acc[i][j]  * invl;
            float v1a = acc[i][j+4]* invl;
            if (accumulate) { op[c0] += v0a; op[c1] += v1a; }
            else            { op[c0] = v0a;  op[c1] = v1a; }
        }
    }
}

__global__ void final_kernel(const float* __restrict__ x, const float* __restrict__ mod,
                             const float* __restrict__ outlin, float* __restrict__ out) {
    int idx = blockIdx.x*blockDim.x + threadIdx.x;
    int col = idx % HIDN;
    out[idx] = x[idx] + mod[2*HIDN + col]*outlin[idx];
}

// ---------------- launcher ----------------
extern "C" void kernel_launch(void* const* d_in, const int* in_sizes, int n_in,
                              void* d_out, int out_size) {
    const float* x          = (const float*)d_in[0];
    const float* vec        = (const float*)d_in[1];
    const float* cosT       = (const float*)d_in[2];
    const float* sinT       = (const float*)d_in[3];
    const float* ref_latent = (const float*)d_in[4];
    const float* ref_cos    = (const float*)d_in[5];
    const float* ref_sin    = (const float*)d_in[6];
    const float* w_mod      = (const float*)d_in[7];
    const float* b_mod      = (const float*)d_in[8];
    const float* w1         = (const float*)d_in[9];
    const float* b1         = (const float*)d_in[10];
    const float* w2         = (const float*)d_in[11];
    const float* b2         = (const float*)d_in[12];
    const float* qn_w       = (const float*)d_in[13];
    const float* kn_w       = (const float*)d_in[14];
    const float* wk_ip      = (const float*)d_in[15];
    const float* bk_ip      = (const float*)d_in[16];
    const float* wv_ip      = (const float*)d_in[17];
    const float* bv_ip      = (const float*)d_in[18];
    const float* ref_kn_w   = (const float*)d_in[19];
    float* out = (float*)d_out;

    float *sv, *modb, *lin1, *qb, *kb, *vb, *attn, *refk, *refv, *outlin;
    __nv_bfloat16 *xh, *xl, *cath, *catl, *rlh, *rll;
    __nv_bfloat16 *w1h, *w1l, *w2h, *w2l, *wkh, *wkl, *wvh, *wvl;
    cudaGetSymbolAddress((void**)&sv,     g_sv);
    cudaGetSymbolAddress((void**)&modb,   g_mod);
    cudaGetSymbolAddress((void**)&xh,     g_xh);
    cudaGetSymbolAddress((void**)&xl,     g_xl);
    cudaGetSymbolAddress((void**)&lin1,   g_lin1);
    cudaGetSymbolAddress((void**)&qb,     g_q);
    cudaGetSymbolAddress((void**)&kb,     g_k);
    cudaGetSymbolAddress((void**)&vb,     g_v);
    cudaGetSymbolAddress((void**)&attn,   g_attn);
    cudaGetSymbolAddress((void**)&cath,   g_cath);
    cudaGetSymbolAddress((void**)&catl,   g_catl);
    cudaGetSymbolAddress((void**)&refk,   g_refk);
    cudaGetSymbolAddress((void**)&refv,   g_refv);
    cudaGetSymbolAddress((void**)&rlh,    g_rlh);
    cudaGetSymbolAddress((void**)&rll,    g_rll);
    cudaGetSymbolAddress((void**)&outlin, g_outlin);
    cudaGetSymbolAddress((void**)&w1h,    g_w1h);
    cudaGetSymbolAddress((void**)&w1l,    g_w1l);
    cudaGetSymbolAddress((void**)&w2h,    g_w2h);
    cudaGetSymbolAddress((void**)&w2l,    g_w2l);
    cudaGetSymbolAddress((void**)&wkh,    g_wkh);
    cudaGetSymbolAddress((void**)&wkl,    g_wkl);
    cudaGetSymbolAddress((void**)&wvh,    g_wvh);
    cudaGetSymbolAddress((void**)&wvl,    g_wvl);

    cudaFuncSetAttribute(flash_attn_kernel,
                         cudaFuncAttributeMaxDynamicSharedMemorySize, FA_SMEM_BYTES);
    cudaFuncSetAttribute(tc_gemm_kernel,
                         cudaFuncAttributeMaxDynamicSharedMemorySize, GK_SMEM_TOTAL);

    dim3 tb(32, 8);

    // 1. mod vector
    silu_kernel<<<12, 256>>>(vec, sv);
    modproj_kernel<<<36, 256>>>(sv, w_mod, b_mod, modb);

    // 2. layernorm + modulate -> split bf16
    ln_mod_kernel<<<LTOT, 256>>>(x, modb, xh, xl);

    // 3. weight transposes + splits
    wsplitT_kernel<<<dim3(L1N/32, HIDN/32), tb>>>(w1, w1h, w1l, HIDN, L1N);
    wsplitT_kernel<<<dim3(HIDN/32, CATN/32), tb>>>(w2, w2h, w2l, CATN, HIDN);
    wsplitT_kernel<<<dim3(HIDN/32, HIDN/32), tb>>>(wk_ip, wkh, wkl, HIDN, HIDN);
    wsplitT_kernel<<<dim3(HIDN/32, HIDN/32), tb>>>(wv_ip, wvh, wvl, HIDN, HIDN);
    split_kernel<<<(REFN*HIDN + 255)/256, 256>>>(ref_latent, rlh, rll, (size_t)REFN*HIDN);

    // 4. lin1 = x_mod @ w1 + b1   (2304 x 21504 x 3072)
    tc_gemm_kernel<<<(LTOT/128)*(L1N/128), 256, GK_SMEM_TOTAL>>>(
        xh, xl, w1h, w1l, b1, lin1, LTOT, L1N, HIDN, LTOT/128);

    // 5. qkv norm/rope + gelu
    qkv_norm_rope_kernel<<<dim3(LTOT, NH), 128>>>(lin1, qn_w, kn_w, cosT, sinT, qb, kb, vb);
    gelu_cat_kernel<<<(LTOT*MLPN)/256, 256>>>(lin1, cath, catl);

    // 6. ref K/V projections (512 x 3072 x 3072) + norm/rope
    tc_gemm_kernel<<<(REFN/128)*(HIDN/128), 256, GK_SMEM_TOTAL>>>(
        rlh, rll, wkh, wkl, bk_ip, refk, REFN, HIDN, HIDN, REFN/128);
    tc_gemm_kernel<<<(REFN/128)*(HIDN/128), 256, GK_SMEM_TOTAL>>>(
        rlh, rll, wvh, wvl, bv_ip, refv, REFN, HIDN, HIDN, REFN/128);
    ref_norm_rope_kernel<<<dim3(REFN, NH), 128>>>(refk, ref_kn_w, ref_cos, ref_sin);

    // 7. attention (self + IP accumulate), then split into cat
    flash_attn_kernel<<<dim3(LTOT/64, NH), 256, FA_SMEM_BYTES>>>(qb, kb, vb, attn, LTOT, HD, 0);
    flash_attn_kernel<<<dim3(LTOT/64, NH), 256, FA_SMEM_BYTES>>>(qb, refk, refv, attn, REFN, HD, 1);
    attn_cat_kernel<<<(LTOT*HIDN)/256, 256>>>(attn, cath, catl);

    // 8. out = cat @ w2 + b2   (2304 x 3072 x 15360)
    tc_gemm_kernel<<<(LTOT/128)*(HIDN/128), 256, GK_SMEM_TOTAL>>>(
        cath, catl, w2h, w2l, b2, outlin, LTOT, HIDN, CATN, LTOT/128);

    // 9. residual
    final_kernel<<<(LTOT*HIDN)/256, 256>>>(x, modb, outlin, out);
}

// round 4
// speedup vs baseline: 3.6275x; 1.5154x over previous
#include <cuda_runtime.h>
#include <cuda_bf16.h>
#include <cstdint>
#include <math.h>

// ---------------- problem constants ----------------
#define LTOT 2304      // IMG + TXT
#define IMGN 2048
#define TXTN 256
#define HIDN 3072
#define NH   24
#define DH   128
#define MLPN 12288
#define REFN 512
#define CATN (HIDN + MLPN)        // 15360
#define L1N  (3*HIDN + MLPN)      // 21504
#define HD   (NH*DH)              // 3072

// ---------------- helpers ----------------
__device__ __forceinline__ uint32_t smem_u32(const void* p) {
    uint32_t a;
    asm("{ .reg .u64 t; cvta.to.shared.u64 t, %1; cvt.u32.u64 %0, t; }" : "=r"(a) : "l"(p));
    return a;
}
#define SMEM_SWIZZLE_128B(byte_offset) ((byte_offset) ^ (((byte_offset) >> 3) & 0x70))

__device__ __forceinline__ void cp16(uint32_t saddr, const void* g) {
    asm volatile("cp.async.cg.shared.global [%0], [%1], 16;" :: "r"(saddr), "l"(g));
}
#define CP_COMMIT() asm volatile("cp.async.commit_group;" ::: "memory")
#define CP_WAIT1()  asm volatile("cp.async.wait_group 1;" ::: "memory")
#define CP_WAIT0()  asm volatile("cp.async.wait_group 0;" ::: "memory")

__device__ __forceinline__ void ldsm4(uint32_t r[4], uint32_t addr) {
    asm volatile("ldmatrix.sync.aligned.m8n8.x4.shared.b16 {%0,%1,%2,%3}, [%4];"
        : "=r"(r[0]), "=r"(r[1]), "=r"(r[2]), "=r"(r[3]) : "r"(addr));
}
__device__ __forceinline__ void ldsm4t(uint32_t r[4], uint32_t addr) {
    asm volatile("ldmatrix.sync.aligned.m8n8.x4.trans.shared.b16 {%0,%1,%2,%3}, [%4];"
        : "=r"(r[0]), "=r"(r[1]), "=r"(r[2]), "=r"(r[3]) : "r"(addr));
}
__device__ __forceinline__ void ldsm2(uint32_t r[2], uint32_t addr) {
    asm volatile("ldmatrix.sync.aligned.m8n8.x2.shared.b16 {%0,%1}, [%2];"
        : "=r"(r[0]), "=r"(r[1]) : "r"(addr));
}
__device__ __forceinline__ void mma16816(float c[4], const uint32_t a[4], const uint32_t b[2]) {
    asm volatile("mma.sync.aligned.m16n8k16.row.col.f32.bf16.bf16.f32 "
        "{%0,%1,%2,%3}, {%4,%5,%6,%7}, {%8,%9}, {%0,%1,%2,%3};"
        : "+f"(c[0]), "+f"(c[1]), "+f"(c[2]), "+f"(c[3])
        : "r"(a[0]), "r"(a[1]), "r"(a[2]), "r"(a[3]), "r"(b[0]), "r"(b[1]));
}

__device__ __forceinline__ void split2(float x, __nv_bfloat16& h, __nv_bfloat16& l) {
    h = __float2bfloat16(x);
    l = __float2bfloat16(x - __bfloat162float(h));
}
__device__ __forceinline__ uint32_t packbf2(float a, float b) {
    __nv_bfloat162 t = __float22bfloat162_rn(make_float2(a, b));
    return *(uint32_t*)&t;
}

// ---------------- device scratch ----------------
__device__ float g_sv[HIDN];
__device__ float g_mod[3*HIDN];
__device__ __nv_bfloat16 g_xh[(size_t)LTOT*HIDN];
__device__ __nv_bfloat16 g_xl[(size_t)LTOT*HIDN];
__device__ float g_lin1[(size_t)LTOT*L1N];
__device__ __nv_bfloat16 g_qb[(size_t)LTOT*HIDN];
__device__ __nv_bfloat16 g_kb[(size_t)LTOT*HIDN];
__device__ __nv_bfloat16 g_vb[(size_t)LTOT*HIDN];
__device__ float g_attn[(size_t)LTOT*HIDN];
__device__ __nv_bfloat16 g_cath[(size_t)LTOT*CATN];
__device__ __nv_bfloat16 g_catl[(size_t)LTOT*CATN];
__device__ float g_refk[(size_t)REFN*HIDN];
__device__ float g_refv[(size_t)REFN*HIDN];
__device__ __nv_bfloat16 g_refkb[(size_t)REFN*HIDN];
__device__ __nv_bfloat16 g_refvb[(size_t)REFN*HIDN];
__device__ __nv_bfloat16 g_rlh[(size_t)REFN*HIDN];
__device__ __nv_bfloat16 g_rll[(size_t)REFN*HIDN];
__device__ float g_outlin[(size_t)LTOT*HIDN];
__device__ __nv_bfloat16 g_w1h[(size_t)L1N*HIDN];
__device__ __nv_bfloat16 g_w1l[(size_t)L1N*HIDN];
__device__ __nv_bfloat16 g_w2h[(size_t)HIDN*CATN];
__device__ __nv_bfloat16 g_w2l[(size_t)HIDN*CATN];
__device__ __nv_bfloat16 g_wkh[(size_t)HIDN*HIDN];
__device__ __nv_bfloat16 g_wkl[(size_t)HIDN*HIDN];
__device__ __nv_bfloat16 g_wvh[(size_t)HIDN*HIDN];
__device__ __nv_bfloat16 g_wvl[(size_t)HIDN*HIDN];

// ---------------- small kernels ----------------
__global__ void silu_kernel(const float* __restrict__ v, float* __restrict__ sv) {
    int i = blockIdx.x*blockDim.x + threadIdx.x;
    if (i < HIDN) { float x = v[i]; sv[i] = x / (1.f + __expf(-x)); }
}

__global__ void modproj_kernel(const float* __restrict__ sv, const float* __restrict__ w,
                               const float* __restrict__ b, float* __restrict__ mod) {
    int n = blockIdx.x*blockDim.x + threadIdx.x;  // < 9216
    float acc = 0.f;
#pragma unroll 8
    for (int k = 0; k < HIDN; k++)
        acc = fmaf(sv[k], w[(size_t)k*(3*HIDN) + n], acc);
    mod[n] = acc + b[n];
}

// layernorm + modulate, write split bf16
__global__ void ln_mod_kernel(const float* __restrict__ x, const float* __restrict__ mod,
                              __nv_bfloat16* __restrict__ xh, __nv_bfloat16* __restrict__ xl) {
    int row = blockIdx.x;
    int tid = threadIdx.x;
    const float* xr = x + (size_t)row*HIDN;
    float s = 0.f, s2 = 0.f;
    for (int i = tid; i < HIDN; i += 256) { float v = xr[i]; s += v; s2 += v*v; }
    __shared__ float rs[256], rs2[256];
    rs[tid] = s; rs2[tid] = s2; __syncthreads();
    for (int o = 128; o > 0; o >>= 1) {
        if (tid < o) { rs[tid] += rs[tid+o]; rs2[tid] += rs2[tid+o]; }
        __syncthreads();
    }
    float mean = rs[0] * (1.f/HIDN);
    float var  = rs2[0] * (1.f/HIDN) - mean*mean;
    float inv  = rsqrtf(var + 1e-6f);
    for (int i = tid; i < HIDN; i += 256) {
        float v = (xr[i] - mean) * inv;
        v = v * (1.f + mod[HIDN + i]) + mod[i];
        __nv_bfloat16 h, l; split2(v, h, l);
        xh[(size_t)row*HIDN + i] = h;
        xl[(size_t)row*HIDN + i] = l;
    }
}

// transpose + split: w[K,N] fp32 -> hi/lo[N,K] bf16
__global__ void wsplitT_kernel(const float* __restrict__ w,
                               __nv_bfloat16* __restrict__ hi, __nv_bfloat16* __restrict__ lo,
                               int K, int N) {
    __shared__ float t[32][33];
    int n0 = blockIdx.x*32, k0 = blockIdx.y*32;
    int tx = threadIdx.x, ty = threadIdx.y;  // 32 x 8
#pragma unroll
    for (int i = 0; i < 32; i += 8)
        t[ty+i][tx] = w[(size_t)(k0+ty+i)*N + n0+tx];
    __syncthreads();
#pragma unroll
    for (int i = 0; i < 32; i += 8) {
        float v = t[tx][ty+i];
        __nv_bfloat16 h, l; split2(v, h, l);
        size_t o = (size_t)(n0+ty+i)*K + k0+tx;
        hi[o] = h; lo[o] = l;
    }
}

__global__ void split_kernel(const float* __restrict__ src,
                             __nv_bfloat16* __restrict__ hi, __nv_bfloat16* __restrict__ lo,
                             size_t n) {
    size_t i = (size_t)blockIdx.x*blockDim.x + threadIdx.x;
    if (i < n) {
        __nv_bfloat16 h, l; split2(src[i], h, l);
        hi[i] = h; lo[i] = l;
    }
}

__global__ void cvt_bf16_kernel(const float* __restrict__ src, __nv_bfloat16* __restrict__ dst,
                                size_t n) {
    size_t i = (size_t)blockIdx.x*blockDim.x + threadIdx.x;
    if (i < n) dst[i] = __float2bfloat16(src[i]);
}

// ---------------- HMMA split-bf16 GEMM (unchanged from round 3) ----------------
#define GS_A   0
#define GS_AL  16384
#define GS_B   32768
#define GS_BL  49152
#define GS_STAGE 65536
#define GK_SMEM_TOTAL (2*GS_STAGE)

__global__ void __launch_bounds__(256, 1) tc_gemm_kernel(
    const __nv_bfloat16* __restrict__ Ahi, const __nv_bfloat16* __restrict__ Alo,
    const __nv_bfloat16* __restrict__ Bhi, const __nv_bfloat16* __restrict__ Blo,
    const float* __restrict__ bias, float* __restrict__ C,
    int M, int N, int K, int m_tiles)
{
    extern __shared__ char smem[];
    uint32_t sb = smem_u32(smem);
    int tid = threadIdx.x;
    int lane = tid & 31, wid = tid >> 5;
    int wm = wid >> 2, wn = wid & 3;

    int mi = blockIdx.x % m_tiles;
    int ni = blockIdx.x / m_tiles;
    int bm = mi * 128, bn = ni * 128;

    float acc[4][4][4];
#pragma unroll
    for (int i = 0; i < 4; i++)
#pragma unroll
        for (int j = 0; j < 4; j++)
#pragma unroll
            for (int r = 0; r < 4; r++) acc[i][j][r] = 0.f;

    int NC = K >> 6;

    auto load_stage = [&](int st, int k0) {
        uint32_t base = sb + st*GS_STAGE;
#pragma unroll
        for (int q = 0; q < 4; q++) {
            int idx = q*256 + tid;
            int r = idx >> 3;
            int ch = (idx & 7) << 4;
            uint32_t sw = SMEM_SWIZZLE_128B((uint32_t)(r*128 + ch));
            const char* pah = (const char*)(Ahi + (size_t)(bm + r)*K + k0) + ch;
            const char* pal = (const char*)(Alo + (size_t)(bm + r)*K + k0) + ch;
            const char* pbh = (const char*)(Bhi + (size_t)(bn + r)*K + k0) + ch;
            const char* pbl = (const char*)(Blo + (size_t)(bn + r)*K + k0) + ch;
            cp16(base + GS_A  + sw, pah);
            cp16(base + GS_AL + sw, pal);
            cp16(base + GS_B  + sw, pbh);
            cp16(base + GS_BL + sw, pbl);
        }
    };

    load_stage(0, 0);
    CP_COMMIT();

    for (int c = 0; c < NC; c++) {
        if (c + 1 < NC) { load_stage((c+1) & 1, (c+1) << 6); CP_COMMIT(); CP_WAIT1(); }
        else            { CP_WAIT0(); }
        __syncthreads();

        uint32_t base = sb + (c & 1)*GS_STAGE;
#pragma unroll
        for (int kk = 0; kk < 4; kk++) {
            uint32_t ah[4][4], al[4][4], bh[4][2], bl[4][2];
            int acol = kk*32 + ((lane >> 4) << 4);
            int arow = wm*64 + (lane & 15);
#pragma unroll
            for (int i = 0; i < 4; i++) {
                uint32_t sw = SMEM_SWIZZLE_128B((uint32_t)((arow + i*16)*128 + acol));
                ldsm4(ah[i], base + GS_A  + sw);
                ldsm4(al[i], base + GS_AL + sw);
            }
            int bcol = kk*32 + (((lane >> 3) & 1) << 4);
            int brow = wn*32 + (lane & 7);
#pragma unroll
            for (int j = 0; j < 4; j++) {
                uint32_t sw = SMEM_SWIZZLE_128B((uint32_t)((brow + j*8)*128 + bcol));
                ldsm2(bh[j], base + GS_B  + sw);
                ldsm2(bl[j], base + GS_BL + sw);
            }
#pragma unroll
            for (int i = 0; i < 4; i++)
#pragma unroll
                for (int j = 0; j < 4; j++) {
                    mma16816(acc[i][j], ah[i], bh[j]);
                    mma16816(acc[i][j], ah[i], bl[j]);
                    mma16816(acc[i][j], al[i], bh[j]);
                }
        }
        __syncthreads();
    }

#pragma unroll
    for (int i = 0; i < 4; i++) {
        int m0 = bm + wm*64 + i*16 + (lane >> 2);
#pragma unroll
        for (int j = 0; j < 4; j++) {
            int n = bn + wn*32 + j*8 + (lane & 3)*2;
            float b0 = bias[n], b1 = bias[n+1];
            float* c0 = C + (size_t)m0*N + n;
            c0[0] = acc[i][j][0] + b0;
            c0[1] = acc[i][j][1] + b1;
            float* c1 = C + (size_t)(m0+8)*N + n;
            c1[0] = acc[i][j][2] + b0;
            c1[1] = acc[i][j][3] + b1;
        }
    }
}

// ---------------- qkv split: rmsnorm q/k + rope -> bf16 ----------------
__global__ void qkv_norm_rope_kernel(const float* __restrict__ lin1,
                                     const float* __restrict__ qn_w, const float* __restrict__ kn_w,
                                     const float* __restrict__ cosT, const float* __restrict__ sinT,
                                     __nv_bfloat16* __restrict__ qo, __nv_bfloat16* __restrict__ ko,
                                     __nv_bfloat16* __restrict__ vo) {
    int t = blockIdx.x, h = blockIdx.y, d = threadIdx.x;
    const float* base = lin1 + (size_t)t*L1N + h*DH;
    float q = base[d];
    float k = base[HIDN + d];
    float v = base[2*HIDN + d];
    float s1 = q*q, s2 = k*k;
#pragma unroll
    for (int o = 16; o > 0; o >>= 1) {
        s1 += __shfl_down_sync(0xffffffffu, s1, o);
        s2 += __shfl_down_sync(0xffffffffu, s2, o);
    }
    __shared__ float red[8];
    int wid = d >> 5, lid = d & 31;
    if (lid == 0) { red[wid] = s1; red[4+wid] = s2; }
    __syncthreads();
    float qs = rsqrtf((red[0]+red[1]+red[2]+red[3]) * (1.f/DH) + 1e-6f);
    float ks = rsqrtf((red[4]+red[5]+red[6]+red[7]) * (1.f/DH) + 1e-6f);
    q = q * qs * qn_w[d];
    k = k * ks * kn_w[d];
    __shared__ float sq[DH], sk[DH];
    sq[d] = q; sk[d] = k;
    __syncthreads();
    if (t < IMGN) {
        int i = d >> 1;
        float c = cosT[t*(DH/2) + i], s = sinT[t*(DH/2) + i];
        float x1 = sq[2*i], x2 = sq[2*i+1];
        q = (d & 1) ? (x1*s + x2*c) : (x1*c - x2*s);
        x1 = sk[2*i]; x2 = sk[2*i+1];
        k = (d & 1) ? (x1*s + x2*c) : (x1*c - x2*s);
    }
    size_t o = ((size_t)t*NH + h)*DH + d;
    qo[o] = __float2bfloat16(q);
    ko[o] = __float2bfloat16(k);
    vo[o] = __float2bfloat16(v);
}

// ref_k: rmsnorm + rope, fp32 in -> bf16 out
__global__ void ref_norm_rope_kernel(const float* __restrict__ rk, const float* __restrict__ w,
                                     const float* __restrict__ cosT, const float* __restrict__ sinT,
                                     __nv_bfloat16* __restrict__ out) {
    int t = blockIdx.x, h = blockIdx.y, d = threadIdx.x;
    const float* base = rk + (size_t)t*HIDN + h*DH;
    float kv = base[d];
    float s = kv*kv;
#pragma unroll
    for (int o = 16; o > 0; o >>= 1) s += __shfl_down_sync(0xffffffffu, s, o);
    __shared__ float red[4];
    int wid = d >> 5, lid = d & 31;
    if (lid == 0) red[wid] = s;
    __syncthreads();
    float kn = kv * rsqrtf((red[0]+red[1]+red[2]+red[3]) * (1.f/DH) + 1e-6f) * w[d];
    __shared__ float sk[DH];
    sk[d] = kn;
    __syncthreads();
    int i = d >> 1;
    float c = cosT[t*(DH/2) + i], sn = sinT[t*(DH/2) + i];
    float x1 = sk[2*i], x2 = sk[2*i+1];
    float r = (d & 1) ? (x1*sn + x2*c) : (x1*c - x2*sn);
    out[(size_t)t*HIDN + h*DH + d] = __float2bfloat16(r);
}

// gelu(mlp) -> cat hi/lo at col offset HIDN
__global__ void gelu_cat_kernel(const float* __restrict__ lin1,
                                __nv_bfloat16* __restrict__ ch, __nv_bfloat16* __restrict__ cl) {
    int idx = blockIdx.x*blockDim.x + threadIdx.x;
    int t = idx / MLPN, j = idx - t*MLPN;
    float x = lin1[(size_t)t*L1N + 3*HIDN + j];
    float g = 0.5f*x*(1.f + tanhf(0.7978845608028654f*(x + 0.044715f*x*x*x)));
    __nv_bfloat16 h, l; split2(g, h, l);
    size_t o = (size_t)t*CATN + HIDN + j;
    ch[o] = h; cl[o] = l;
}

// attn fp32 -> cat hi/lo at cols [0, HIDN)
__global__ void attn_cat_kernel(const float* __restrict__ attn,
                                __nv_bfloat16* __restrict__ ch, __nv_bfloat16* __restrict__ cl) {
    int idx = blockIdx.x*blockDim.x + threadIdx.x;
    int t = idx / HIDN, j = idx - t*HIDN;
    __nv_bfloat16 h, l; split2(attn[idx], h, l);
    size_t o = (size_t)t*CATN + j;
    ch[o] = h; cl[o] = l;
}

// ---------------- HMMA flash attention ----------------
// 128 q-rows/CTA, 8 warps x 16 rows, 64-key tiles, double-buffered cp.async K/V.
// SMEM: Q 32KB | K 2x16KB | V 2x16KB = 96KB
#define FAH_Q 0
#define FAH_K 32768
#define FAH_V 65536
#define FAH_SMEM 98304

__global__ void __launch_bounds__(256, 1) fa_hmma_kernel(
    const __nv_bfloat16* __restrict__ Q, const __nv_bfloat16* __restrict__ K,
    const __nv_bfloat16* __restrict__ V, float* __restrict__ O,
    int Lk, int accumulate)
{
    extern __shared__ char smem[];
    uint32_t sb = smem_u32(smem);
    int tid = threadIdx.x, lane = tid & 31, wid = tid >> 5;
    int h = blockIdx.y;
    int q0 = blockIdx.x * 128;
    const float scale = 0.08838834764831845f;   // 1/sqrt(128)

    // load Q tile (128 rows x 128 dims bf16, two 128B-half tiles)
#pragma unroll
    for (int qi = 0; qi < 8; qi++) {
        int idx = qi*256 + tid;
        int r = idx >> 4, ch = idx & 15;
        uint32_t ad = sb + FAH_Q + (ch>>3)*16384 + SMEM_SWIZZLE_128B((uint32_t)(r*128 + (ch&7)*16));
        cp16(ad, Q + (size_t)(q0+r)*HD + h*DH + ch*8);
    }
    CP_COMMIT();

    auto load_kv = [&](int s, int k0) {
        uint32_t kbs = sb + FAH_K + s*16384;
        uint32_t vbs = sb + FAH_V + s*16384;
#pragma unroll
        for (int qi = 0; qi < 4; qi++) {
            int idx = qi*256 + tid;
            int r = idx >> 4, ch = idx & 15;
            uint32_t off = (ch>>3)*8192 + SMEM_SWIZZLE_128B((uint32_t)(r*128 + (ch&7)*16));
            cp16(kbs + off, K + (size_t)(k0+r)*HD + h*DH + ch*8);
            cp16(vbs + off, V + (size_t)(k0+r)*HD + h*DH + ch*8);
        }
    };
    load_kv(0, 0);
    CP_COMMIT();

    CP_WAIT1();            // Q group complete
    __syncthreads();

    // Q fragments (register-resident for whole kernel)
    uint32_t qa[8][4];
    {
        int row = wid*16 + (lane & 7) + ((lane >> 3) & 1)*8;
#pragma unroll
        for (int kc = 0; kc < 8; kc++) {
            int d = kc*16 + ((lane >> 4) & 1)*8;
            uint32_t ad = sb + FAH_Q + (d>>6)*16384 + SMEM_SWIZZLE_128B((uint32_t)(row*128 + (d&63)*2));
            ldsm4(qa[kc], ad);
        }
    }

    float o[16][4];
#pragma unroll
    for (int i = 0; i < 16; i++)
#pragma unroll
        for (int j = 0; j < 4; j++) o[i][j] = 0.f;
    float m0 = -1e30f, m1 = -1e30f, l0 = 0.f, l1 = 0.f;

    int T = Lk >> 6;
    for (int t = 0; t < T; t++) {
        if (t + 1 < T) { load_kv((t+1) & 1, (t+1) << 6); CP_COMMIT(); CP_WAIT1(); }
        else           { CP_WAIT0(); }
        __syncthreads();
        uint32_t kst = sb + FAH_K + (t & 1)*16384;
        uint32_t vst = sb + FAH_V + (t & 1)*16384;

        // ---- S = Q K^T (16 x 64 per warp) ----
        float c[8][4];
#pragma unroll
        for (int i = 0; i < 8; i++)
#pragma unroll
            for (int j = 0; j < 4; j++) c[i][j] = 0.f;

        int krow = (lane & 7) + ((lane >> 4) & 1)*8;
        int kpl  = ((lane >> 3) & 1)*8;
#pragma unroll
        for (int nb2 = 0; nb2 < 4; nb2++) {
            int row = nb2*16 + krow;
#pragma unroll
            for (int kc = 0; kc < 8; kc++) {
                uint32_t bf[4];
                int d = kc*16 + kpl;
                uint32_t ad = kst + (d>>6)*8192 + SMEM_SWIZZLE_128B((uint32_t)(row*128 + (d&63)*2));
                ldsm4(bf, ad);
                mma16816(c[nb2*2],   qa[kc], bf);
                mma16816(c[nb2*2+1], qa[kc], bf + 2);
            }
        }

        // ---- online softmax (rows r=lane>>2 and r+8 per thread) ----
        float mn0 = m0, mn1 = m1;
#pragma unroll
        for (int nb = 0; nb < 8; nb++) {
            c[nb][0] *= scale; c[nb][1] *= scale; c[nb][2] *= scale; c[nb][3] *= scale;
            mn0 = fmaxf(mn0, fmaxf(c[nb][0], c[nb][1]));
            mn1 = fmaxf(mn1, fmaxf(c[nb][2], c[nb][3]));
        }
        mn0 = fmaxf(mn0, __shfl_xor_sync(0xffffffffu, mn0, 1));
        mn0 = fmaxf(mn0, __shfl_xor_sync(0xffffffffu, mn0, 2));
        mn1 = fmaxf(mn1, __shfl_xor_sync(0xffffffffu, mn1, 1));
        mn1 = fmaxf(mn1, __shfl_xor_sync(0xffffffffu, mn1, 2));
        float a0 = __expf(m0 - mn0), a1 = __expf(m1 - mn1);
        m0 = mn0; m1 = mn1;
        float s0 = 0.f, s1 = 0.f;
#pragma unroll
        for (int nb = 0; nb < 8; nb++) {
            c[nb][0] = __expf(c[nb][0] - m0);
            c[nb][1] = __expf(c[nb][1] - m0);
            c[nb][2] = __expf(c[nb][2] - m1);
            c[nb][3] = __expf(c[nb][3] - m1);
            s0 += c[nb][0] + c[nb][1];
            s1 += c[nb][2] + c[nb][3];
        }
        s0 += __shfl_xor_sync(0xffffffffu, s0, 1);
        s0 += __shfl_xor_sync(0xffffffffu, s0, 2);
        s1 += __shfl_xor_sync(0xffffffffu, s1, 1);
        s1 += __shfl_xor_sync(0xffffffffu, s1, 2);
        l0 = l0*a0 + s0;
        l1 = l1*a1 + s1;

        // rescale o
#pragma unroll
        for (int nb = 0; nb < 16; nb++) {
            o[nb][0] *= a0; o[nb][1] *= a0; o[nb][2] *= a1; o[nb][3] *= a1;
        }

        // pack P into A fragments (c-frag -> a-frag identity)
        uint32_t pa[4][4];
#pragma unroll
        for (int kc2 = 0; kc2 < 4; kc2++) {
            pa[kc2][0] = packbf2(c[2*kc2][0],   c[2*kc2][1]);
            pa[kc2][1] = packbf2(c[2*kc2][2],   c[2*kc2][3]);
            pa[kc2][2] = packbf2(c[2*kc2+1][0], c[2*kc2+1][1]);
            pa[kc2][3] = packbf2(c[2*kc2+1][2], c[2*kc2+1][3]);
        }

        // ---- O += P V ----
        int vrow = (lane & 7) + ((lane >> 3) & 1)*8;
        int npl  = ((lane >> 4) & 1)*8;
#pragma unroll
        for (int kc2 = 0; kc2 < 4; kc2++) {
            int row = kc2*16 + vrow;
#pragma unroll
            for (int nbp = 0; nbp < 8; nbp++) {
                uint32_t bf[4];
                int n = nbp*16 + npl;
                uint32_t ad = vst + (n>>6)*8192 + SMEM_SWIZZLE_128B((uint32_t)(row*128 + (n&63)*2));
                ldsm4t(bf, ad);
                mma16816(o[nbp*2],   pa[kc2], bf);
                mma16816(o[nbp*2+1], pa[kc2], bf + 2);
            }
        }
        __syncthreads();
    }

    // ---- epilogue ----
    float inv0 = 1.f / l0, inv1 = 1.f / l1;
    int r0 = q0 + wid*16 + (lane >> 2);
#pragma unroll
    for (int nb = 0; nb < 16; nb++) {
        int n = h*DH + nb*8 + (lane & 3)*2;
        float* p0 = O + (size_t)r0*HD + n;
        float* p1 = O + (size_t)(r0+8)*HD + n;
        if (accumulate) {
            p0[0] += o[nb][0]*inv0; p0[1] += o[nb][1]*inv0;
            p1[0] += o[nb][2]*inv1; p1[1] += o[nb][3]*inv1;
        } else {
            p0[0] = o[nb][0]*inv0; p0[1] = o[nb][1]*inv0;
            p1[0] = o[nb][2]*inv1; p1[1] = o[nb][3]*inv1;
        }
    }
}

__global__ void final_kernel(const float* __restrict__ x, const float* __restrict__ mod,
                             const float* __restrict__ outlin, float* __restrict__ out) {
    int idx = blockIdx.x*blockDim.x + threadIdx.x;
    int col = idx % HIDN;
    out[idx] = x[idx] + mod[2*HIDN + col]*outlin[idx];
}

// ---------------- launcher ----------------
extern "C" void kernel_launch(void* const* d_in, const int* in_sizes, int n_in,
                              void* d_out, int out_size) {
    const float* x          = (const float*)d_in[0];
    const float* vec        = (const float*)d_in[1];
    const float* cosT       = (const float*)d_in[2];
    const float* sinT       = (const float*)d_in[3];
    const float* ref_latent = (const float*)d_in[4];
    const float* ref_cos    = (const float*)d_in[5];
    const float* ref_sin    = (const float*)d_in[6];
    const float* w_mod      = (const float*)d_in[7];
    const float* b_mod      = (const float*)d_in[8];
    const float* w1         = (const float*)d_in[9];
    const float* b1         = (const float*)d_in[10];
    const float* w2         = (const float*)d_in[11];
    const float* b2         = (const float*)d_in[12];
    const float* qn_w       = (const float*)d_in[13];
    const float* kn_w       = (const float*)d_in[14];
    const float* wk_ip      = (const float*)d_in[15];
    const float* bk_ip      = (const float*)d_in[16];
    const float* wv_ip      = (const float*)d_in[17];
    const float* bv_ip      = (const float*)d_in[18];
    const float* ref_kn_w   = (const float*)d_in[19];
    float* out = (float*)d_out;

    float *sv, *modb, *lin1, *attn, *refk, *refv, *outlin;
    __nv_bfloat16 *xh, *xl, *cath, *catl, *rlh, *rll;
    __nv_bfloat16 *qb, *kb, *vb, *refkb, *refvb;
    __nv_bfloat16 *w1h, *w1l, *w2h, *w2l, *wkh, *wkl, *wvh, *wvl;
    cudaGetSymbolAddress((void**)&sv,     g_sv);
    cudaGetSymbolAddress((void**)&modb,   g_mod);
    cudaGetSymbolAddress((void**)&xh,     g_xh);
    cudaGetSymbolAddress((void**)&xl,     g_xl);
    cudaGetSymbolAddress((void**)&lin1,   g_lin1);
    cudaGetSymbolAddress((void**)&qb,     g_qb);
    cudaGetSymbolAddress((void**)&kb,     g_kb);
    cudaGetSymbolAddress((void**)&vb,     g_vb);
    cudaGetSymbolAddress((void**)&attn,   g_attn);
    cudaGetSymbolAddress((void**)&cath,   g_cath);
    cudaGetSymbolAddress((void**)&catl,   g_catl);
    cudaGetSymbolAddress((void**)&refk,   g_refk);
    cudaGetSymbolAddress((void**)&refv,   g_refv);
    cudaGetSymbolAddress((void**)&refkb,  g_refkb);
    cudaGetSymbolAddress((void**)&refvb,  g_refvb);
    cudaGetSymbolAddress((void**)&rlh,    g_rlh);
    cudaGetSymbolAddress((void**)&rll,    g_rll);
    cudaGetSymbolAddress((void**)&outlin, g_outlin);
    cudaGetSymbolAddress((void**)&w1h,    g_w1h);
    cudaGetSymbolAddress((void**)&w1l,    g_w1l);
    cudaGetSymbolAddress((void**)&w2h,    g_w2h);
    cudaGetSymbolAddress((void**)&w2l,    g_w2l);
    cudaGetSymbolAddress((void**)&wkh,    g_wkh);
    cudaGetSymbolAddress((void**)&wkl,    g_wkl);
    cudaGetSymbolAddress((void**)&wvh,    g_wvh);
    cudaGetSymbolAddress((void**)&wvl,    g_wvl);

    cudaFuncSetAttribute(tc_gemm_kernel,
                         cudaFuncAttributeMaxDynamicSharedMemorySize, GK_SMEM_TOTAL);
    cudaFuncSetAttribute(fa_hmma_kernel,
                         cudaFuncAttributeMaxDynamicSharedMemorySize, FAH_SMEM);

    dim3 tb(32, 8);

    // 1. mod vector
    silu_kernel<<<12, 256>>>(vec, sv);
    modproj_kernel<<<36, 256>>>(sv, w_mod, b_mod, modb);

    // 2. layernorm + modulate -> split bf16
    ln_mod_kernel<<<LTOT, 256>>>(x, modb, xh, xl);

    // 3. weight transposes + splits
    wsplitT_kernel<<<dim3(L1N/32, HIDN/32), tb>>>(w1, w1h, w1l, HIDN, L1N);
    wsplitT_kernel<<<dim3(HIDN/32, CATN/32), tb>>>(w2, w2h, w2l, CATN, HIDN);
    wsplitT_kernel<<<dim3(HIDN/32, HIDN/32), tb>>>(wk_ip, wkh, wkl, HIDN, HIDN);
    wsplitT_kernel<<<dim3(HIDN/32, HIDN/32), tb>>>(wv_ip, wvh, wvl, HIDN, HIDN);
    split_kernel<<<(REFN*HIDN + 255)/256, 256>>>(ref_latent, rlh, rll, (size_t)REFN*HIDN);

    // 4. lin1 = x_mod @ w1 + b1   (2304 x 21504 x 3072)
    tc_gemm_kernel<<<(LTOT/128)*(L1N/128), 256, GK_SMEM_TOTAL>>>(
        xh, xl, w1h, w1l, b1, lin1, LTOT, L1N, HIDN, LTOT/128);

    // 5. qkv norm/rope -> bf16 ; gelu
    qkv_norm_rope_kernel<<<dim3(LTOT, NH), 128>>>(lin1, qn_w, kn_w, cosT, sinT, qb, kb, vb);
    gelu_cat_kernel<<<(LTOT*MLPN)/256, 256>>>(lin1, cath, catl);

    // 6. ref K/V projections (512 x 3072 x 3072) + norm/rope -> bf16
    tc_gemm_kernel<<<(REFN/128)*(HIDN/128), 256, GK_SMEM_TOTAL>>>(
        rlh, rll, wkh, wkl, bk_ip, refk, REFN, HIDN, HIDN, REFN/128);
    tc_gemm_kernel<<<(REFN/128)*(HIDN/128), 256, GK_SMEM_TOTAL>>>(
        rlh, rll, wvh, wvl, bv_ip, refv, REFN, HIDN, HIDN, REFN/128);
    ref_norm_rope_kernel<<<dim3(REFN, NH), 128>>>(refk, ref_kn_w, ref_cos, ref_sin, refkb);
    cvt_bf16_kernel<<<(REFN*HIDN + 255)/256, 256>>>(refv, refvb, (size_t)REFN*HIDN);

    // 7. HMMA attention (self + IP accumulate), then split into cat
    fa_hmma_kernel<<<dim3(LTOT/128, NH), 256, FAH_SMEM>>>(qb, kb, vb, attn, LTOT, 0);
    fa_hmma_kernel<<<dim3(LTOT/128, NH), 256, FAH_SMEM>>>(qb, refkb, refvb, attn, REFN, 1);
    attn_cat_kernel<<<(LTOT*HIDN)/256, 256>>>(attn, cath, catl);

    // 8. out = cat @ w2 + b2   (2304 x 3072 x 15360)
    tc_gemm_kernel<<<(LTOT/128)*(HIDN/128), 256, GK_SMEM_TOTAL>>>(
        cath, catl, w2h, w2l, b2, outlin, LTOT, HIDN, CATN, LTOT/128);

    // 9. residual
    final_kernel<<<(LTOT*HIDN)/256, 256>>>(x, modb, outlin, out);
}

// round 6
// speedup vs baseline: 8.5131x; 2.3468x over previous
#include <cuda_runtime.h>
#include <cuda_fp16.h>
#include <cstdint>
#include <math.h>

// ---------------- problem constants ----------------
#define LTOT 2304      // IMG + TXT
#define IMGN 2048
#define TXTN 256
#define HIDN 3072
#define NH   24
#define DH   128
#define MLPN 12288
#define REFN 512
#define CATN (HIDN + MLPN)        // 15360
#define L1N  (3*HIDN + MLPN)      // 21504
#define HD   (NH*DH)              // 3072

// ---------------- helpers ----------------
__device__ __forceinline__ uint32_t smem_u32(const void* p) {
    uint32_t a;
    asm("{ .reg .u64 t; cvta.to.shared.u64 t, %1; cvt.u32.u64 %0, t; }" : "=r"(a) : "l"(p));
    return a;
}
#define SMEM_SWIZZLE_128B(byte_offset) ((byte_offset) ^ (((byte_offset) >> 3) & 0x70))

__device__ __forceinline__ void cp16(uint32_t saddr, const void* g) {
    asm volatile("cp.async.cg.shared.global [%0], [%1], 16;" :: "r"(saddr), "l"(g));
}
#define CP_COMMIT() asm volatile("cp.async.commit_group;" ::: "memory")
#define CP_WAIT1()  asm volatile("cp.async.wait_group 1;" ::: "memory")
#define CP_WAIT0()  asm volatile("cp.async.wait_group 0;" ::: "memory")

__device__ __forceinline__ void ldsm4(uint32_t r[4], uint32_t addr) {
    asm volatile("ldmatrix.sync.aligned.m8n8.x4.shared.b16 {%0,%1,%2,%3}, [%4];"
        : "=r"(r[0]), "=r"(r[1]), "=r"(r[2]), "=r"(r[3]) : "r"(addr));
}
__device__ __forceinline__ void ldsm4t(uint32_t r[4], uint32_t addr) {
    asm volatile("ldmatrix.sync.aligned.m8n8.x4.trans.shared.b16 {%0,%1,%2,%3}, [%4];"
        : "=r"(r[0]), "=r"(r[1]), "=r"(r[2]), "=r"(r[3]) : "r"(addr));
}
// fp16 HMMA, fp32 accumulate
__device__ __forceinline__ void mma16816(float c[4], const uint32_t a[4], const uint32_t b[2]) {
    asm volatile("mma.sync.aligned.m16n8k16.row.col.f32.f16.f16.f32 "
        "{%0,%1,%2,%3}, {%4,%5,%6,%7}, {%8,%9}, {%0,%1,%2,%3};"
        : "+f"(c[0]), "+f"(c[1]), "+f"(c[2]), "+f"(c[3])
        : "r"(a[0]), "r"(a[1]), "r"(a[2]), "r"(a[3]), "r"(b[0]), "r"(b[1]));
}
__device__ __forceinline__ uint32_t packh2(float a, float b) {
    __half2 t = __floats2half2_rn(a, b);
    return *(uint32_t*)&t;
}

// ---------------- device scratch ----------------
__device__ float g_sv[HIDN];
__device__ float g_mod[3*HIDN];
__device__ __half g_xb[(size_t)LTOT*HIDN];
__device__ float g_lin1[(size_t)LTOT*L1N];
__device__ __half g_qb[(size_t)LTOT*HIDN];
__device__ __half g_kb[(size_t)LTOT*HIDN];
__device__ __half g_vb[(size_t)LTOT*HIDN];
__device__ float g_attn[(size_t)LTOT*HIDN];
__device__ __half g_cat[(size_t)LTOT*CATN];
__device__ float g_refk[(size_t)REFN*HIDN];
__device__ float g_refv[(size_t)REFN*HIDN];
__device__ __half g_refkb[(size_t)REFN*HIDN];
__device__ __half g_refvb[(size_t)REFN*HIDN];
__device__ __half g_rlb[(size_t)REFN*HIDN];
__device__ float g_outlin[(size_t)LTOT*HIDN];
__device__ __half g_w1b[(size_t)L1N*HIDN];
__device__ __half g_w2b[(size_t)HIDN*CATN];
__device__ __half g_wkb[(size_t)HIDN*HIDN];
__device__ __half g_wvb[(size_t)HIDN*HIDN];

// ---------------- small kernels ----------------
__global__ void silu_kernel(const float* __restrict__ v, float* __restrict__ sv) {
    int i = blockIdx.x*blockDim.x + threadIdx.x;
    if (i < HIDN) { float x = v[i]; sv[i] = x / (1.f + __expf(-x)); }
}

// mod = silu(vec) @ w_mod + b_mod, k-split across 8 warps per block
__global__ void modproj_kernel(const float* __restrict__ sv, const float* __restrict__ w,
                               const float* __restrict__ b, float* __restrict__ mod) {
    __shared__ float red[8][32];
    int nx = threadIdx.x & 31, ky = threadIdx.x >> 5;
    int n = blockIdx.x*32 + nx;
    float acc = 0.f;
    for (int k = ky; k < HIDN; k += 8)
        acc = fmaf(sv[k], w[(size_t)k*(3*HIDN) + n], acc);
    red[ky][nx] = acc;
    __syncthreads();
    if (ky == 0) {
        float s = acc;
#pragma unroll
        for (int i = 1; i < 8; i++) s += red[i][nx];
        mod[n] = s + b[n];
    }
}

// layernorm + modulate -> fp16
__global__ void ln_mod_kernel(const float* __restrict__ x, const float* __restrict__ mod,
                              __half* __restrict__ xb) {
    int row = blockIdx.x;
    int tid = threadIdx.x;
    const float* xr = x + (size_t)row*HIDN;
    float s = 0.f, s2 = 0.f;
    for (int i = tid; i < HIDN; i += 256) { float v = xr[i]; s += v; s2 += v*v; }
    __shared__ float rs[256], rs2[256];
    rs[tid] = s; rs2[tid] = s2; __syncthreads();
    for (int o = 128; o > 0; o >>= 1) {
        if (tid < o) { rs[tid] += rs[tid+o]; rs2[tid] += rs2[tid+o]; }
        __syncthreads();
    }
    float mean = rs[0] * (1.f/HIDN);
    float var  = rs2[0] * (1.f/HIDN) - mean*mean;
    float inv  = rsqrtf(var + 1e-6f);
    for (int i = tid; i < HIDN; i += 256) {
        float v = (xr[i] - mean) * inv;
        v = v * (1.f + mod[HIDN + i]) + mod[i];
        xb[(size_t)row*HIDN + i] = __float2half_rn(v);
    }
}

// transpose + convert: w[K,N] fp32 -> [N,K] fp16
__global__ void wcvtT_kernel(const float* __restrict__ w, __half* __restrict__ o,
                             int K, int N) {
    __shared__ float t[32][33];
    int n0 = blockIdx.x*32, k0 = blockIdx.y*32;
    int tx = threadIdx.x, ty = threadIdx.y;  // 32 x 8
#pragma unroll
    for (int i = 0; i < 32; i += 8)
        t[ty+i][tx] = w[(size_t)(k0+ty+i)*N + n0+tx];
    __syncthreads();
#pragma unroll
    for (int i = 0; i < 32; i += 8)
        o[(size_t)(n0+ty+i)*K + k0+tx] = __float2half_rn(t[tx][ty+i]);
}

__global__ void cvt_h_kernel(const float* __restrict__ src, __half* __restrict__ dst,
                             size_t n) {
    size_t i = (size_t)blockIdx.x*blockDim.x + threadIdx.x;
    if (i < n) dst[i] = __float2half_rn(src[i]);
}

// ---------------- HMMA fp16 GEMM ----------------
// C[M,N] = A[M,K] @ B[N,K]^T + bias.  Tile 128x128, K-chunk 64, 8 warps (64x32 each),
// double-buffered cp.async.  Stage: A 16KB | B 16KB = 32KB; 2 stages = 64KB -> 2 CTAs/SM.
#define GS_B     16384
#define GS_STAGE 32768
#define GK_SMEM_TOTAL (2*GS_STAGE)

__global__ void __launch_bounds__(256, 2) tc_gemm_kernel(
    const __half* __restrict__ A, const __half* __restrict__ B,
    const float* __restrict__ bias, float* __restrict__ C,
    int M, int N, int K, int m_tiles)
{
    extern __shared__ char smem[];
    uint32_t sb = smem_u32(smem);
    int tid = threadIdx.x;
    int lane = tid & 31, wid = tid >> 5;
    int wm = wid >> 2, wn = wid & 3;   // warp tile: rows wm*64, cols wn*32

    int mi = blockIdx.x % m_tiles;
    int ni = blockIdx.x / m_tiles;
    int bm = mi * 128, bn = ni * 128;

    float acc[4][4][4];
#pragma unroll
    for (int i = 0; i < 4; i++)
#pragma unroll
        for (int j = 0; j < 4; j++)
#pragma unroll
            for (int r = 0; r < 4; r++) acc[i][j][r] = 0.f;

    int NC = K >> 6;

    auto load_stage = [&](int st, int k0) {
        uint32_t base = sb + st*GS_STAGE;
#pragma unroll
        for (int q = 0; q < 4; q++) {
            int idx = q*256 + tid;
            int r = idx >> 3;
            int ch = (idx & 7) << 4;
            uint32_t sw = SMEM_SWIZZLE_128B((uint32_t)(r*128 + ch));
            cp16(base + sw,        (const char*)(A + (size_t)(bm + r)*K + k0) + ch);
            cp16(base + GS_B + sw, (const char*)(B + (size_t)(bn + r)*K + k0) + ch);
        }
    };

    load_stage(0, 0);
    CP_COMMIT();

    for (int c = 0; c < NC; c++) {
        if (c + 1 < NC) { load_stage((c+1) & 1, (c+1) << 6); CP_COMMIT(); CP_WAIT1(); }
        else            { CP_WAIT0(); }
        __syncthreads();

        uint32_t base = sb + (c & 1)*GS_STAGE;
        int arow = wm*64 + (lane & 15);
        int apl  = ((lane >> 4) & 1) << 4;
        int brow = wn*32 + ((lane >> 4) & 1)*8 + (lane & 7);
        int bpl  = ((lane >> 3) & 1) << 4;
#pragma unroll
        for (int kk = 0; kk < 4; kk++) {
            uint32_t a[4][4], b[2][4];
#pragma unroll
            for (int i = 0; i < 4; i++) {
                uint32_t sw = SMEM_SWIZZLE_128B((uint32_t)((arow + i*16)*128 + kk*32 + apl));
                ldsm4(a[i], base + sw);
            }
#pragma unroll
            for (int jp = 0; jp < 2; jp++) {
                uint32_t sw = SMEM_SWIZZLE_128B((uint32_t)((brow + jp*16)*128 + kk*32 + bpl));
                ldsm4(b[jp], base + GS_B + sw);
            }
#pragma unroll
            for (int i = 0; i < 4; i++) {
                mma16816(acc[i][0], a[i], b[0]);
                mma16816(acc[i][1], a[i], b[0] + 2);
                mma16816(acc[i][2], a[i], b[1]);
                mma16816(acc[i][3], a[i], b[1] + 2);
            }
        }
        __syncthreads();
    }

#pragma unroll
    for (int i = 0; i < 4; i++) {
        int m0 = bm + wm*64 + i*16 + (lane >> 2);
#pragma unroll
        for (int j = 0; j < 4; j++) {
            int n = bn + wn*32 + j*8 + (lane & 3)*2;
            float b0 = bias[n], b1 = bias[n+1];
            float* c0 = C + (size_t)m0*N + n;
            c0[0] = acc[i][j][0] + b0;
            c0[1] = acc[i][j][1] + b1;
            float* c1 = C + (size_t)(m0+8)*N + n;
            c1[0] = acc[i][j][2] + b0;
            c1[1] = acc[i][j][3] + b1;
        }
    }
}

// ---------------- qkv split: rmsnorm q/k + rope -> fp16 ----------------
__global__ void qkv_norm_rope_kernel(const float* __restrict__ lin1,
                                     const float* __restrict__ qn_w, const float* __restrict__ kn_w,
                                     const float* __restrict__ cosT, const float* __restrict__ sinT,
                                     __half* __restrict__ qo, __half* __restrict__ ko,
                                     __half* __restrict__ vo) {
    int t = blockIdx.x, h = blockIdx.y, d = threadIdx.x;
    const float* base = lin1 + (size_t)t*L1N + h*DH;
    float q = base[d];
    float k = base[HIDN + d];
    float v = base[2*HIDN + d];
    float s1 = q*q, s2 = k*k;
#pragma unroll
    for (int o = 16; o > 0; o >>= 1) {
        s1 += __shfl_down_sync(0xffffffffu, s1, o);
        s2 += __shfl_down_sync(0xffffffffu, s2, o);
    }
    __shared__ float red[8];
    int wid = d >> 5, lid = d & 31;
    if (lid == 0) { red[wid] = s1; red[4+wid] = s2; }
    __syncthreads();
    float qs = rsqrtf((red[0]+red[1]+red[2]+red[3]) * (1.f/DH) + 1e-6f);
    float ks = rsqrtf((red[4]+red[5]+red[6]+red[7]) * (1.f/DH) + 1e-6f);
    q = q * qs * qn_w[d];
    k = k * ks * kn_w[d];
    __shared__ float sq[DH], sk[DH];
    sq[d] = q; sk[d] = k;
    __syncthreads();
    if (t < IMGN) {
        int i = d >> 1;
        float c = cosT[t*(DH/2) + i], s = sinT[t*(DH/2) + i];
        float x1 = sq[2*i], x2 = sq[2*i+1];
        q = (d & 1) ? (x1*s + x2*c) : (x1*c - x2*s);
        x1 = sk[2*i]; x2 = sk[2*i+1];
        k = (d & 1) ? (x1*s + x2*c) : (x1*c - x2*s);
    }
    size_t o = ((size_t)t*NH + h)*DH + d;
    qo[o] = __float2half_rn(q);
    ko[o] = __float2half_rn(k);
    vo[o] = __float2half_rn(v);
}

// ref_k: rmsnorm + rope, fp32 in -> fp16 out
__global__ void ref_norm_rope_kernel(const float* __restrict__ rk, const float* __restrict__ w,
                                     const float* __restrict__ cosT, const float* __restrict__ sinT,
                                     __half* __restrict__ out) {
    int t = blockIdx.x, h = blockIdx.y, d = threadIdx.x;
    const float* base = rk + (size_t)t*HIDN + h*DH;
    float kv = base[d];
    float s = kv*kv;
#pragma unroll
    for (int o = 16; o > 0; o >>= 1) s += __shfl_down_sync(0xffffffffu, s, o);
    __shared__ float red[4];
    int wid = d >> 5, lid = d & 31;
    if (lid == 0) red[wid] = s;
    __syncthreads();
    float kn = kv * rsqrtf((red[0]+red[1]+red[2]+red[3]) * (1.f/DH) + 1e-6f) * w[d];
    __shared__ float sk[DH];
    sk[d] = kn;
    __syncthreads();
    int i = d >> 1;
    float c = cosT[t*(DH/2) + i], sn = sinT[t*(DH/2) + i];
    float x1 = sk[2*i], x2 = sk[2*i+1];
    float r = (d & 1) ? (x1*sn + x2*c) : (x1*c - x2*sn);
    out[(size_t)t*HIDN + h*DH + d] = __float2half_rn(r);
}

// gelu(mlp) -> cat fp16 at col offset HIDN
__global__ void gelu_cat_kernel(const float* __restrict__ lin1, __half* __restrict__ cat) {
    int idx = blockIdx.x*blockDim.x + threadIdx.x;
    int t = idx / MLPN, j = idx - t*MLPN;
    float x = lin1[(size_t)t*L1N + 3*HIDN + j];
    float g = 0.5f*x*(1.f + tanhf(0.7978845608028654f*(x + 0.044715f*x*x*x)));
    cat[(size_t)t*CATN + HIDN + j] = __float2half_rn(g);
}

// attn fp32 -> cat fp16 at cols [0, HIDN)
__global__ void attn_cat_kernel(const float* __restrict__ attn, __half* __restrict__ cat) {
    int idx = blockIdx.x*blockDim.x + threadIdx.x;
    int t = idx / HIDN, j = idx - t*HIDN;
    cat[(size_t)t*CATN + j] = __float2half_rn(attn[idx]);
}

// ---------------- HMMA flash attention (fp16 operands) ----------------
#define FAH_Q 0
#define FAH_K 32768
#define FAH_V 65536
#define FAH_SMEM 98304

__global__ void __launch_bounds__(256, 1) fa_hmma_kernel(
    const __half* __restrict__ Q, const __half* __restrict__ K,
    const __half* __restrict__ V, float* __restrict__ O,
    int Lk, int accumulate)
{
    extern __shared__ char smem[];
    uint32_t sb = smem_u32(smem);
    int tid = threadIdx.x, lane = tid & 31, wid = tid >> 5;
    int h = blockIdx.y;
    int q0 = blockIdx.x * 128;
    const float scale = 0.08838834764831845f;

#pragma unroll
    for (int qi = 0; qi < 8; qi++) {
        int idx = qi*256 + tid;
        int r = idx >> 4, ch = idx & 15;
        uint32_t ad = sb + FAH_Q + (ch>>3)*16384 + SMEM_SWIZZLE_128B((uint32_t)(r*128 + (ch&7)*16));
        cp16(ad, Q + (size_t)(q0+r)*HD + h*DH + ch*8);
    }
    CP_COMMIT();

    auto load_kv = [&](int s, int k0) {
        uint32_t kbs = sb + FAH_K + s*16384;
        uint32_t vbs = sb + FAH_V + s*16384;
#pragma unroll
        for (int qi = 0; qi < 4; qi++) {
            int idx = qi*256 + tid;
            int r = idx >> 4, ch = idx & 15;
            uint32_t off = (ch>>3)*8192 + SMEM_SWIZZLE_128B((uint32_t)(r*128 + (ch&7)*16));
            cp16(kbs + off, K + (size_t)(k0+r)*HD + h*DH + ch*8);
            cp16(vbs + off, V + (size_t)(k0+r)*HD + h*DH + ch*8);
        }
    };
    load_kv(0, 0);
    CP_COMMIT();

    CP_WAIT1();
    __syncthreads();

    uint32_t qa[8][4];
    {
        int row = wid*16 + (lane & 7) + ((lane >> 3) & 1)*8;
#pragma unroll
        for (int kc = 0; kc < 8; kc++) {
            int d = kc*16 + ((lane >> 4) & 1)*8;
            uint32_t ad = sb + FAH_Q + (d>>6)*16384 + SMEM_SWIZZLE_128B((uint32_t)(row*128 + (d&63)*2));
            ldsm4(qa[kc], ad);
        }
    }

    float o[16][4];
#pragma unroll
    for (int i = 0; i < 16; i++)
#pragma unroll
        for (int j = 0; j < 4; j++) o[i][j] = 0.f;
    float m0 = -1e30f, m1 = -1e30f, l0 = 0.f, l1 = 0.f;

    int T = Lk >> 6;
    for (int t = 0; t < T; t++) {
        if (t + 1 < T) { load_kv((t+1) & 1, (t+1) << 6); CP_COMMIT(); CP_WAIT1(); }
        else           { CP_WAIT0(); }
        __syncthreads();
        uint32_t kst = sb + FAH_K + (t & 1)*16384;
        uint32_t vst = sb + FAH_V + (t & 1)*16384;

        float c[8][4];
#pragma unroll
        for (int i = 0; i < 8; i++)
#pragma unroll
            for (int j = 0; j < 4; j++) c[i][j] = 0.f;

        int krow = (lane & 7) + ((lane >> 4) & 1)*8;
        int kpl  = ((lane >> 3) & 1)*8;
#pragma unroll
        for (int nb2 = 0; nb2 < 4; nb2++) {
            int row = nb2*16 + krow;
#pragma unroll
            for (int kc = 0; kc < 8; kc++) {
                uint32_t bf[4];
                int d = kc*16 + kpl;
                uint32_t ad = kst + (d>>6)*8192 + SMEM_SWIZZLE_128B((uint32_t)(row*128 + (d&63)*2));
                ldsm4(bf, ad);
                mma16816(c[nb2*2],   qa[kc], bf);
                mma16816(c[nb2*2+1], qa[kc], bf + 2);
            }
        }

        float mn0 = m0, mn1 = m1;
#pragma unroll
        for (int nb = 0; nb < 8; nb++) {
            c[nb][0] *= scale; c[nb][1] *= scale; c[nb][2] *= scale; c[nb][3] *= scale;
            mn0 = fmaxf(mn0, fmaxf(c[nb][0], c[nb][1]));
            mn1 = fmaxf(mn1, fmaxf(c[nb][2], c[nb][3]));
        }
        mn0 = fmaxf(mn0, __shfl_xor_sync(0xffffffffu, mn0, 1));
        mn0 = fmaxf(mn0, __shfl_xor_sync(0xffffffffu, mn0, 2));
        mn1 = fmaxf(mn1, __shfl_xor_sync(0xffffffffu, mn1, 1));
        mn1 = fmaxf(mn1, __shfl_xor_sync(0xffffffffu, mn1, 2));
        float a0 = __expf(m0 - mn0), a1 = __expf(m1 - mn1);
        m0 = mn0; m1 = mn1;
        float s0 = 0.f, s1 = 0.f;
#pragma unroll
        for (int nb = 0; nb < 8; nb++) {
            c[nb][0] = __expf(c[nb][0] - m0);
            c[nb][1] = __expf(c[nb][1] - m0);
            c[nb][2] = __expf(c[nb][2] - m1);
            c[nb][3] = __expf(c[nb][3] - m1);
            s0 += c[nb][0] + c[nb][1];
            s1 += c[nb][2] + c[nb][3];
        }
        s0 += __shfl_xor_sync(0xffffffffu, s0, 1);
        s0 += __shfl_xor_sync(0xffffffffu, s0, 2);
        s1 += __shfl_xor_sync(0xffffffffu, s1, 1);
        s1 += __shfl_xor_sync(0xffffffffu, s1, 2);
        l0 = l0*a0 + s0;
        l1 = l1*a1 + s1;

#pragma unroll
        for (int nb = 0; nb < 16; nb++) {
            o[nb][0] *= a0; o[nb][1] *= a0; o[nb][2] *= a1; o[nb][3] *= a1;
        }

        uint32_t pa[4][4];
#pragma unroll
        for (int kc2 = 0; kc2 < 4; kc2++) {
            pa[kc2][0] = packh2(c[2*kc2][0],   c[2*kc2][1]);
            pa[kc2][1] = packh2(c[2*kc2][2],   c[2*kc2][3]);
            pa[kc2][2] = packh2(c[2*kc2+1][0], c[2*kc2+1][1]);
            pa[kc2][3] = packh2(c[2*kc2+1][2], c[2*kc2+1][3]);
        }

        int vrow = (lane & 7) + ((lane >> 3) & 1)*8;
        int npl  = ((lane >> 4) & 1)*8;
#pragma unroll
        for (int kc2 = 0; kc2 < 4; kc2++) {
            int row = kc2*16 + vrow;
#pragma unroll
            for (int nbp = 0; nbp < 8; nbp++) {
                uint32_t bf[4];
                int n = nbp*16 + npl;
                uint32_t ad = vst + (n>>6)*8192 + SMEM_SWIZZLE_128B((uint32_t)(row*128 + (n&63)*2));
                ldsm4t(bf, ad);
                mma16816(o[nbp*2],   pa[kc2], bf);
                mma16816(o[nbp*2+1], pa[kc2], bf + 2);
            }
        }
        __syncthreads();
    }

    float inv0 = 1.f / l0, inv1 = 1.f / l1;
    int r0 = q0 + wid*16 + (lane >> 2);
#pragma unroll
    for (int nb = 0; nb < 16; nb++) {
        int n = h*DH + nb*8 + (lane & 3)*2;
        float* p0 = O + (size_t)r0*HD + n;
        float* p1 = O + (size_t)(r0+8)*HD + n;
        if (accumulate) {
            p0[0] += o[nb][0]*inv0; p0[1] += o[nb][1]*inv0;
            p1[0] += o[nb][2]*inv1; p1[1] += o[nb][3]*inv1;
        } else {
            p0[0] = o[nb][0]*inv0; p0[1] = o[nb][1]*inv0;
            p1[0] = o[nb][2]*inv1; p1[1] = o[nb][3]*inv1;
        }
    }
}

__global__ void final_kernel(const float* __restrict__ x, const float* __restrict__ mod,
                             const float* __restrict__ outlin, float* __restrict__ out) {
    int idx = blockIdx.x*blockDim.x + threadIdx.x;
    int col = idx % HIDN;
    out[idx] = x[idx] + mod[2*HIDN + col]*outlin[idx];
}

// ---------------- launcher ----------------
extern "C" void kernel_launch(void* const* d_in, const int* in_sizes, int n_in,
                              void* d_out, int out_size) {
    const float* x          = (const float*)d_in[0];
    const float* vec        = (const float*)d_in[1];
    const float* cosT       = (const float*)d_in[2];
    const float* sinT       = (const float*)d_in[3];
    const float* ref_latent = (const float*)d_in[4];
    const float* ref_cos    = (const float*)d_in[5];
    const float* ref_sin    = (const float*)d_in[6];
    const float* w_mod      = (const float*)d_in[7];
    const float* b_mod      = (const float*)d_in[8];
    const float* w1         = (const float*)d_in[9];
    const float* b1         = (const float*)d_in[10];
    const float* w2         = (const float*)d_in[11];
    const float* b2         = (const float*)d_in[12];
    const float* qn_w       = (const float*)d_in[13];
    const float* kn_w       = (const float*)d_in[14];
    const float* wk_ip      = (const float*)d_in[15];
    const float* bk_ip      = (const float*)d_in[16];
    const float* wv_ip      = (const float*)d_in[17];
    const float* bv_ip      = (const float*)d_in[18];
    const float* ref_kn_w   = (const float*)d_in[19];
    float* out = (float*)d_out;

    float *sv, *modb, *lin1, *attn, *refk, *refv, *outlin;
    __half *xb, *cat, *rlb, *qb, *kb, *vb, *refkb, *refvb;
    __half *w1b, *w2b, *wkb, *wvb;
    cudaGetSymbolAddress((void**)&sv,     g_sv);
    cudaGetSymbolAddress((void**)&modb,   g_mod);
    cudaGetSymbolAddress((void**)&xb,     g_xb);
    cudaGetSymbolAddress((void**)&lin1,   g_lin1);
    cudaGetSymbolAddress((void**)&qb,     g_qb);
    cudaGetSymbolAddress((void**)&kb,     g_kb);
    cudaGetSymbolAddress((void**)&vb,     g_vb);
    cudaGetSymbolAddress((void**)&attn,   g_attn);
    cudaGetSymbolAddress((void**)&cat,    g_cat);
    cudaGetSymbolAddress((void**)&refk,   g_refk);
    cudaGetSymbolAddress((void**)&refv,   g_refv);
    cudaGetSymbolAddress((void**)&refkb,  g_refkb);
    cudaGetSymbolAddress((void**)&refvb,  g_refvb);
    cudaGetSymbolAddress((void**)&rlb,    g_rlb);
    cudaGetSymbolAddress((void**)&outlin, g_outlin);
    cudaGetSymbolAddress((void**)&w1b,    g_w1b);
    cudaGetSymbolAddress((void**)&w2b,    g_w2b);
    cudaGetSymbolAddress((void**)&wkb,    g_wkb);
    cudaGetSymbolAddress((void**)&wvb,    g_wvb);

    cudaFuncSetAttribute(tc_gemm_kernel,
                         cudaFuncAttributeMaxDynamicSharedMemorySize, GK_SMEM_TOTAL);
    cudaFuncSetAttribute(fa_hmma_kernel,
                         cudaFuncAttributeMaxDynamicSharedMemorySize, FAH_SMEM);

    dim3 tb(32, 8);

    // 1. mod vector
    silu_kernel<<<12, 256>>>(vec, sv);
    modproj_kernel<<<(3*HIDN)/32, 256>>>(sv, w_mod, b_mod, modb);

    // 2. layernorm + modulate -> fp16
    ln_mod_kernel<<<LTOT, 256>>>(x, modb, xb);

    // 3. weight transposes + converts
    wcvtT_kernel<<<dim3(L1N/32, HIDN/32), tb>>>(w1, w1b, HIDN, L1N);
    wcvtT_kernel<<<dim3(HIDN/32, CATN/32), tb>>>(w2, w2b, CATN, HIDN);
    wcvtT_kernel<<<dim3(HIDN/32, HIDN/32), tb>>>(wk_ip, wkb, HIDN, HIDN);
    wcvtT_kernel<<<dim3(HIDN/32, HIDN/32), tb>>>(wv_ip, wvb, HIDN, HIDN);
    cvt_h_kernel<<<(REFN*HIDN + 255)/256, 256>>>(ref_latent, rlb, (size_t)REFN*HIDN);

    // 4. lin1 = x_mod @ w1 + b1   (2304 x 21504 x 3072)
    tc_gemm_kernel<<<(LTOT/128)*(L1N/128), 256, GK_SMEM_TOTAL>>>(
        xb, w1b, b1, lin1, LTOT, L1N, HIDN, LTOT/128);

    // 5. qkv norm/rope -> fp16 ; gelu
    qkv_norm_rope_kernel<<<dim3(LTOT, NH), 128>>>(lin1, qn_w, kn_w, cosT, sinT, qb, kb, vb);
    gelu_cat_kernel<<<(LTOT*MLPN)/256, 256>>>(lin1, cat);

    // 6. ref K/V projections (512 x 3072 x 3072) + norm/rope -> fp16
    tc_gemm_kernel<<<(REFN/128)*(HIDN/128), 256, GK_SMEM_TOTAL>>>(
        rlb, wkb, bk_ip, refk, REFN, HIDN, HIDN, REFN/128);
    tc_gemm_kernel<<<(REFN/128)*(HIDN/128), 256, GK_SMEM_TOTAL>>>(
        rlb, wvb, bv_ip, refv, REFN, HIDN, HIDN, REFN/128);
    ref_norm_rope_kernel<<<dim3(REFN, NH), 128>>>(refk, ref_kn_w, ref_cos, ref_sin, refkb);
    cvt_h_kernel<<<(REFN*HIDN + 255)/256, 256>>>(refv, refvb, (size_t)REFN*HIDN);

    // 7. HMMA attention (self + IP accumulate), then convert into cat
    fa_hmma_kernel<<<dim3(LTOT/128, NH), 256, FAH_SMEM>>>(qb, kb, vb, attn, LTOT, 0);
    fa_hmma_kernel<<<dim3(LTOT/128, NH), 256, FAH_SMEM>>>(qb, refkb, refvb, attn, REFN, 1);
    attn_cat_kernel<<<(LTOT*HIDN)/256, 256>>>(attn, cat);

    // 8. out = cat @ w2 + b2   (2304 x 3072 x 15360)
    tc_gemm_kernel<<<(LTOT/128)*(HIDN/128), 256, GK_SMEM_TOTAL>>>(
        cat, w2b, b2, outlin, LTOT, HIDN, CATN, LTOT/128);

    // 9. residual
    final_kernel<<<(LTOT*HIDN)/256, 256>>>(x, modb, outlin, out);
}

// round 7
// speedup vs baseline: 9.3760x; 1.1014x over previous
#include <cuda_runtime.h>
#include <cuda_fp16.h>
#include <cstdint>
#include <math.h>

// ---------------- problem constants ----------------
#define LTOT 2304      // IMG + TXT
#define IMGN 2048
#define TXTN 256
#define HIDN 3072
#define NH   24
#define DH   128
#define MLPN 12288
#define REFN 512
#define CATN (HIDN + MLPN)        // 15360
#define L1N  (3*HIDN + MLPN)      // 21504
#define HD   (NH*DH)              // 3072

// ---------------- helpers ----------------
__device__ __forceinline__ uint32_t smem_u32(const void* p) {
    uint32_t a;
    asm("{ .reg .u64 t; cvta.to.shared.u64 t, %1; cvt.u32.u64 %0, t; }" : "=r"(a) : "l"(p));
    return a;
}
#define SMEM_SWIZZLE_128B(byte_offset) ((byte_offset) ^ (((byte_offset) >> 3) & 0x70))

__device__ __forceinline__ void cp16(uint32_t saddr, const void* g) {
    asm volatile("cp.async.cg.shared.global [%0], [%1], 16;" :: "r"(saddr), "l"(g));
}
#define CP_COMMIT() asm volatile("cp.async.commit_group;" ::: "memory")
#define CP_WAIT1()  asm volatile("cp.async.wait_group 1;" ::: "memory")
#define CP_WAIT0()  asm volatile("cp.async.wait_group 0;" ::: "memory")

__device__ __forceinline__ void ldsm4(uint32_t r[4], uint32_t addr) {
    asm volatile("ldmatrix.sync.aligned.m8n8.x4.shared.b16 {%0,%1,%2,%3}, [%4];"
        : "=r"(r[0]), "=r"(r[1]), "=r"(r[2]), "=r"(r[3]) : "r"(addr));
}
__device__ __forceinline__ void ldsm4t(uint32_t r[4], uint32_t addr) {
    asm volatile("ldmatrix.sync.aligned.m8n8.x4.trans.shared.b16 {%0,%1,%2,%3}, [%4];"
        : "=r"(r[0]), "=r"(r[1]), "=r"(r[2]), "=r"(r[3]) : "r"(addr));
}
__device__ __forceinline__ void mma16816(float c[4], const uint32_t a[4], const uint32_t b[2]) {
    asm volatile("mma.sync.aligned.m16n8k16.row.col.f32.f16.f16.f32 "
        "{%0,%1,%2,%3}, {%4,%5,%6,%7}, {%8,%9}, {%0,%1,%2,%3};"
        : "+f"(c[0]), "+f"(c[1]), "+f"(c[2]), "+f"(c[3])
        : "r"(a[0]), "r"(a[1]), "r"(a[2]), "r"(a[3]), "r"(b[0]), "r"(b[1]));
}
__device__ __forceinline__ uint32_t packh2(float a, float b) {
    __half2 t = __floats2half2_rn(a, b);
    return *(uint32_t*)&t;
}
__device__ __forceinline__ float gelu_f(float x) {
    return 0.5f*x*(1.f + tanhf(0.7978845608028654f*(x + 0.044715f*x*x*x)));
}

// ---------------- device scratch ----------------
__device__ float g_sv[HIDN];
__device__ float g_mod[3*HIDN];
__device__ __half g_xb[(size_t)LTOT*HIDN];
__device__ float g_lin1[(size_t)LTOT*(3*HIDN)];      // qkv part only (fp32)
__device__ __half g_qb[(size_t)LTOT*HIDN];
__device__ __half g_kb[(size_t)LTOT*HIDN];
__device__ __half g_vb[(size_t)LTOT*HIDN];
__device__ float g_attn[(size_t)LTOT*HIDN];
__device__ __half g_cat[(size_t)LTOT*CATN];
__device__ float g_refk[(size_t)REFN*HIDN];
__device__ float g_refv[(size_t)REFN*HIDN];
__device__ __half g_refkb[(size_t)REFN*HIDN];
__device__ __half g_refvb[(size_t)REFN*HIDN];
__device__ __half g_rlb[(size_t)REFN*HIDN];
__device__ __half g_w1b[(size_t)L1N*HIDN];
__device__ __half g_w2b[(size_t)HIDN*CATN];
__device__ __half g_wkb[(size_t)HIDN*HIDN];
__device__ __half g_wvb[(size_t)HIDN*HIDN];

// ---------------- small kernels ----------------
__global__ void silu_kernel(const float* __restrict__ v, float* __restrict__ sv) {
    int i = blockIdx.x*blockDim.x + threadIdx.x;
    if (i < HIDN) { float x = v[i]; sv[i] = x / (1.f + __expf(-x)); }
}

__global__ void modproj_kernel(const float* __restrict__ sv, const float* __restrict__ w,
                               const float* __restrict__ b, float* __restrict__ mod) {
    __shared__ float red[8][32];
    int nx = threadIdx.x & 31, ky = threadIdx.x >> 5;
    int n = blockIdx.x*32 + nx;
    float acc = 0.f;
    for (int k = ky; k < HIDN; k += 8)
        acc = fmaf(sv[k], w[(size_t)k*(3*HIDN) + n], acc);
    red[ky][nx] = acc;
    __syncthreads();
    if (ky == 0) {
        float s = acc;
#pragma unroll
        for (int i = 1; i < 8; i++) s += red[i][nx];
        mod[n] = s + b[n];
    }
}

__global__ void ln_mod_kernel(const float* __restrict__ x, const float* __restrict__ mod,
                              __half* __restrict__ xb) {
    int row = blockIdx.x;
    int tid = threadIdx.x;
    const float* xr = x + (size_t)row*HIDN;
    float s = 0.f, s2 = 0.f;
    for (int i = tid; i < HIDN; i += 256) { float v = xr[i]; s += v; s2 += v*v; }
    __shared__ float rs[256], rs2[256];
    rs[tid] = s; rs2[tid] = s2; __syncthreads();
    for (int o = 128; o > 0; o >>= 1) {
        if (tid < o) { rs[tid] += rs[tid+o]; rs2[tid] += rs2[tid+o]; }
        __syncthreads();
    }
    float mean = rs[0] * (1.f/HIDN);
    float var  = rs2[0] * (1.f/HIDN) - mean*mean;
    float inv  = rsqrtf(var + 1e-6f);
    for (int i = tid; i < HIDN; i += 256) {
        float v = (xr[i] - mean) * inv;
        v = v * (1.f + mod[HIDN + i]) + mod[i];
        xb[(size_t)row*HIDN + i] = __float2half_rn(v);
    }
}

// transpose + convert: w[K,N] fp32 -> [N,K] fp16.  Tile: 64 k-rows x 32 n-cols.
// Conflict-free smem (row pad 66 halves), 128B-coalesced loads AND stores.
__global__ void wcvtT_kernel(const float* __restrict__ w, __half* __restrict__ o,
                             int K, int N) {
    __shared__ __half t[32][66];
    int n0 = blockIdx.x*32, k0 = blockIdx.y*64;
    int tx = threadIdx.x, ty = threadIdx.y;  // 32 x 8
#pragma unroll
    for (int i = 0; i < 8; i++) {
        int k = ty + i*8;
        t[tx][k] = __float2half_rn(w[(size_t)(k0+k)*N + n0 + tx]);
    }
    __syncthreads();
#pragma unroll
    for (int i = 0; i < 4; i++) {
        int n = i*8 + ty;
        __half2 v = *(__half2*)&t[n][2*tx];
        *(__half2*)&o[(size_t)(n0+n)*K + k0 + 2*tx] = v;
    }
}

__global__ void cvt_h_kernel(const float* __restrict__ src, __half* __restrict__ dst,
                             size_t n) {
    size_t i = (size_t)blockIdx.x*blockDim.x + threadIdx.x;
    if (i < n) dst[i] = __float2half_rn(src[i]);
}

// ---------------- HMMA fp16 GEMM with fused epilogues ----------------
// C[M,N] = A[M,K] @ B[N,K]^T + bias
// mode 0 (PLAIN): C fp32
// mode 1 (LIN1):  N=L1N; cols < 3*HIDN -> lin1 fp32 (stride 3*HIDN); cols >= -> gelu fp16 into cat
// mode 2 (OUT):   out = xres + gate[n]*(acc+bias), fp32, stride N
#define GS_B     16384
#define GS_STAGE 32768
#define GK_SMEM_TOTAL (2*GS_STAGE)

__global__ void __launch_bounds__(256, 2) tc_gemm_kernel(
    const __half* __restrict__ A, const __half* __restrict__ B,
    const float* __restrict__ bias, float* __restrict__ C,
    __half* __restrict__ cat, const float* __restrict__ xres,
    const float* __restrict__ gate,
    int M, int N, int K, int m_tiles, int mode)
{
    extern __shared__ char smem[];
    uint32_t sb = smem_u32(smem);
    int tid = threadIdx.x;
    int lane = tid & 31, wid = tid >> 5;
    int wm = wid >> 2, wn = wid & 3;

    int mi = blockIdx.x % m_tiles;
    int ni = blockIdx.x / m_tiles;
    int bm = mi * 128, bn = ni * 128;

    float acc[4][4][4];
#pragma unroll
    for (int i = 0; i < 4; i++)
#pragma unroll
        for (int j = 0; j < 4; j++)
#pragma unroll
            for (int r = 0; r < 4; r++) acc[i][j][r] = 0.f;

    int NC = K >> 6;

    auto load_stage = [&](int st, int k0) {
        uint32_t base = sb + st*GS_STAGE;
#pragma unroll
        for (int q = 0; q < 4; q++) {
            int idx = q*256 + tid;
            int r = idx >> 3;
            int ch = (idx & 7) << 4;
            uint32_t sw = SMEM_SWIZZLE_128B((uint32_t)(r*128 + ch));
            cp16(base + sw,        (const char*)(A + (size_t)(bm + r)*K + k0) + ch);
            cp16(base + GS_B + sw, (const char*)(B + (size_t)(bn + r)*K + k0) + ch);
        }
    };

    load_stage(0, 0);
    CP_COMMIT();

    for (int c = 0; c < NC; c++) {
        if (c + 1 < NC) { load_stage((c+1) & 1, (c+1) << 6); CP_COMMIT(); CP_WAIT1(); }
        else            { CP_WAIT0(); }
        __syncthreads();

        uint32_t base = sb + (c & 1)*GS_STAGE;
        int arow = wm*64 + (lane & 15);
        int apl  = ((lane >> 4) & 1) << 4;
        int brow = wn*32 + ((lane >> 4) & 1)*8 + (lane & 7);
        int bpl  = ((lane >> 3) & 1) << 4;
#pragma unroll
        for (int kk = 0; kk < 4; kk++) {
            uint32_t a[4][4], b[2][4];
#pragma unroll
            for (int i = 0; i < 4; i++) {
                uint32_t sw = SMEM_SWIZZLE_128B((uint32_t)((arow + i*16)*128 + kk*32 + apl));
                ldsm4(a[i], base + sw);
            }
#pragma unroll
            for (int jp = 0; jp < 2; jp++) {
                uint32_t sw = SMEM_SWIZZLE_128B((uint32_t)((brow + jp*16)*128 + kk*32 + bpl));
                ldsm4(b[jp], base + GS_B + sw);
            }
#pragma unroll
            for (int i = 0; i < 4; i++) {
                mma16816(acc[i][0], a[i], b[0]);
                mma16816(acc[i][1], a[i], b[0] + 2);
                mma16816(acc[i][2], a[i], b[1]);
                mma16816(acc[i][3], a[i], b[1] + 2);
            }
        }
        __syncthreads();
    }

#pragma unroll
    for (int i = 0; i < 4; i++) {
        int m0 = bm + wm*64 + i*16 + (lane >> 2);
#pragma unroll
        for (int j = 0; j < 4; j++) {
            int n = bn + wn*32 + j*8 + (lane & 3)*2;
            float b0 = bias[n], b1 = bias[n+1];
            float v00 = acc[i][j][0] + b0, v01 = acc[i][j][1] + b1;
            float v10 = acc[i][j][2] + b0, v11 = acc[i][j][3] + b1;
            if (mode == 0) {
                float* c0 = C + (size_t)m0*N + n;
                float* c1 = C + (size_t)(m0+8)*N + n;
                c0[0] = v00; c0[1] = v01; c1[0] = v10; c1[1] = v11;
            } else if (mode == 1) {
                if (bn < 3*HIDN) {
                    float* c0 = C + (size_t)m0*(3*HIDN) + n;
                    float* c1 = C + (size_t)(m0+8)*(3*HIDN) + n;
                    c0[0] = v00; c0[1] = v01; c1[0] = v10; c1[1] = v11;
                } else {
                    int nc = HIDN + (n - 3*HIDN);
                    __half* c0 = cat + (size_t)m0*CATN + nc;
                    __half* c1 = cat + (size_t)(m0+8)*CATN + nc;
                    c0[0] = __float2half_rn(gelu_f(v00));
                    c0[1] = __float2half_rn(gelu_f(v01));
                    c1[0] = __float2half_rn(gelu_f(v10));
                    c1[1] = __float2half_rn(gelu_f(v11));
                }
            } else {
                float g0 = gate[n], g1 = gate[n+1];
                const float* x0 = xres + (size_t)m0*N + n;
                const float* x1 = xres + (size_t)(m0+8)*N + n;
                float* c0 = C + (size_t)m0*N + n;
                float* c1 = C + (size_t)(m0+8)*N + n;
                c0[0] = x0[0] + g0*v00; c0[1] = x0[1] + g1*v01;
                c1[0] = x1[0] + g0*v10; c1[1] = x1[1] + g1*v11;
            }
        }
    }
}

// ---------------- qkv split: rmsnorm q/k + rope -> fp16 ----------------
__global__ void qkv_norm_rope_kernel(const float* __restrict__ lin1,
                                     const float* __restrict__ qn_w, const float* __restrict__ kn_w,
                                     const float* __restrict__ cosT, const float* __restrict__ sinT,
                                     __half* __restrict__ qo, __half* __restrict__ ko,
                                     __half* __restrict__ vo) {
    int t = blockIdx.x, h = blockIdx.y, d = threadIdx.x;
    const float* base = lin1 + (size_t)t*(3*HIDN) + h*DH;
    float q = base[d];
    float k = base[HIDN + d];
    float v = base[2*HIDN + d];
    float s1 = q*q, s2 = k*k;
#pragma unroll
    for (int o = 16; o > 0; o >>= 1) {
        s1 += __shfl_down_sync(0xffffffffu, s1, o);
        s2 += __shfl_down_sync(0xffffffffu, s2, o);
    }
    __shared__ float red[8];
    int wid = d >> 5, lid = d & 31;
    if (lid == 0) { red[wid] = s1; red[4+wid] = s2; }
    __syncthreads();
    float qs = rsqrtf((red[0]+red[1]+red[2]+red[3]) * (1.f/DH) + 1e-6f);
    float ks = rsqrtf((red[4]+red[5]+red[6]+red[7]) * (1.f/DH) + 1e-6f);
    q = q * qs * qn_w[d];
    k = k * ks * kn_w[d];
    __shared__ float sq[DH], sk[DH];
    sq[d] = q; sk[d] = k;
    __syncthreads();
    if (t < IMGN) {
        int i = d >> 1;
        float c = cosT[t*(DH/2) + i], s = sinT[t*(DH/2) + i];
        float x1 = sq[2*i], x2 = sq[2*i+1];
        q = (d & 1) ? (x1*s + x2*c) : (x1*c - x2*s);
        x1 = sk[2*i]; x2 = sk[2*i+1];
        k = (d & 1) ? (x1*s + x2*c) : (x1*c - x2*s);
    }
    size_t o = ((size_t)t*NH + h)*DH + d;
    qo[o] = __float2half_rn(q);
    ko[o] = __float2half_rn(k);
    vo[o] = __float2half_rn(v);
}

__global__ void ref_norm_rope_kernel(const float* __restrict__ rk, const float* __restrict__ w,
                                     const float* __restrict__ cosT, const float* __restrict__ sinT,
                                     __half* __restrict__ out) {
    int t = blockIdx.x, h = blockIdx.y, d = threadIdx.x;
    const float* base = rk + (size_t)t*HIDN + h*DH;
    float kv = base[d];
    float s = kv*kv;
#pragma unroll
    for (int o = 16; o > 0; o >>= 1) s += __shfl_down_sync(0xffffffffu, s, o);
    __shared__ float red[4];
    int wid = d >> 5, lid = d & 31;
    if (lid == 0) red[wid] = s;
    __syncthreads();
    float kn = kv * rsqrtf((red[0]+red[1]+red[2]+red[3]) * (1.f/DH) + 1e-6f) * w[d];
    __shared__ float sk[DH];
    sk[d] = kn;
    __syncthreads();
    int i = d >> 1;
    float c = cosT[t*(DH/2) + i], sn = sinT[t*(DH/2) + i];
    float x1 = sk[2*i], x2 = sk[2*i+1];
    float r = (d & 1) ? (x1*sn + x2*c) : (x1*c - x2*sn);
    out[(size_t)t*HIDN + h*DH + d] = __float2half_rn(r);
}

// ---------------- HMMA flash attention ----------------
// mode 0: write fp32 O (attn scratch).  mode 1: read attn_in, add, write fp16 cat.
#define FAH_Q 0
#define FAH_K 32768
#define FAH_V 65536
#define FAH_SMEM 98304

__global__ void __launch_bounds__(256, 1) fa_hmma_kernel(
    const __half* __restrict__ Q, const __half* __restrict__ K,
    const __half* __restrict__ V, float* __restrict__ O,
    const float* __restrict__ attn_in, __half* __restrict__ cat,
    int Lk, int mode)
{
    extern __shared__ char smem[];
    uint32_t sb = smem_u32(smem);
    int tid = threadIdx.x, lane = tid & 31, wid = tid >> 5;
    int h = blockIdx.y;
    int q0 = blockIdx.x * 128;
    const float scale = 0.08838834764831845f;

#pragma unroll
    for (int qi = 0; qi < 8; qi++) {
        int idx = qi*256 + tid;
        int r = idx >> 4, ch = idx & 15;
        uint32_t ad = sb + FAH_Q + (ch>>3)*16384 + SMEM_SWIZZLE_128B((uint32_t)(r*128 + (ch&7)*16));
        cp16(ad, Q + (size_t)(q0+r)*HD + h*DH + ch*8);
    }
    CP_COMMIT();

    auto load_kv = [&](int s, int k0) {
        uint32_t kbs = sb + FAH_K + s*16384;
        uint32_t vbs = sb + FAH_V + s*16384;
#pragma unroll
        for (int qi = 0; qi < 4; qi++) {
            int idx = qi*256 + tid;
            int r = idx >> 4, ch = idx & 15;
            uint32_t off = (ch>>3)*8192 + SMEM_SWIZZLE_128B((uint32_t)(r*128 + (ch&7)*16));
            cp16(kbs + off, K + (size_t)(k0+r)*HD + h*DH + ch*8);
            cp16(vbs + off, V + (size_t)(k0+r)*HD + h*DH + ch*8);
        }
    };
    load_kv(0, 0);
    CP_COMMIT();

    CP_WAIT1();
    __syncthreads();

    uint32_t qa[8][4];
    {
        int row = wid*16 + (lane & 7) + ((lane >> 3) & 1)*8;
#pragma unroll
        for (int kc = 0; kc < 8; kc++) {
            int d = kc*16 + ((lane >> 4) & 1)*8;
            uint32_t ad = sb + FAH_Q + (d>>6)*16384 + SMEM_SWIZZLE_128B((uint32_t)(row*128 + (d&63)*2));
            ldsm4(qa[kc], ad);
        }
    }

    float o[16][4];
#pragma unroll
    for (int i = 0; i < 16; i++)
#pragma unroll
        for (int j = 0; j < 4; j++) o[i][j] = 0.f;
    float m0 = -1e30f, m1 = -1e30f, l0 = 0.f, l1 = 0.f;

    int T = Lk >> 6;
    for (int t = 0; t < T; t++) {
        if (t + 1 < T) { load_kv((t+1) & 1, (t+1) << 6); CP_COMMIT(); CP_WAIT1(); }
        else           { CP_WAIT0(); }
        __syncthreads();
        uint32_t kst = sb + FAH_K + (t & 1)*16384;
        uint32_t vst = sb + FAH_V + (t & 1)*16384;

        float c[8][4];
#pragma unroll
        for (int i = 0; i < 8; i++)
#pragma unroll
            for (int j = 0; j < 4; j++) c[i][j] = 0.f;

        int krow = (lane & 7) + ((lane >> 4) & 1)*8;
        int kpl  = ((lane >> 3) & 1)*8;
#pragma unroll
        for (int nb2 = 0; nb2 < 4; nb2++) {
            int row = nb2*16 + krow;
#pragma unroll
            for (int kc = 0; kc < 8; kc++) {
                uint32_t bf[4];
                int d = kc*16 + kpl;
                uint32_t ad = kst + (d>>6)*8192 + SMEM_SWIZZLE_128B((uint32_t)(row*128 + (d&63)*2));
                ldsm4(bf, ad);
                mma16816(c[nb2*2],   qa[kc], bf);
                mma16816(c[nb2*2+1], qa[kc], bf + 2);
            }
        }

        float mn0 = m0, mn1 = m1;
#pragma unroll
        for (int nb = 0; nb < 8; nb++) {
            c[nb][0] *= scale; c[nb][1] *= scale; c[nb][2] *= scale; c[nb][3] *= scale;
            mn0 = fmaxf(mn0, fmaxf(c[nb][0], c[nb][1]));
            mn1 = fmaxf(mn1, fmaxf(c[nb][2], c[nb][3]));
        }
        mn0 = fmaxf(mn0, __shfl_xor_sync(0xffffffffu, mn0, 1));
        mn0 = fmaxf(mn0, __shfl_xor_sync(0xffffffffu, mn0, 2));
        mn1 = fmaxf(mn1, __shfl_xor_sync(0xffffffffu, mn1, 1));
        mn1 = fmaxf(mn1, __shfl_xor_sync(0xffffffffu, mn1, 2));
        float a0 = __expf(m0 - mn0), a1 = __expf(m1 - mn1);
        m0 = mn0; m1 = mn1;
        float s0 = 0.f, s1 = 0.f;
#pragma unroll
        for (int nb = 0; nb < 8; nb++) {
            c[nb][0] = __expf(c[nb][0] - m0);
            c[nb][1] = __expf(c[nb][1] - m0);
            c[nb][2] = __expf(c[nb][2] - m1);
            c[nb][3] = __expf(c[nb][3] - m1);
            s0 += c[nb][0] + c[nb][1];
            s1 += c[nb][2] + c[nb][3];
        }
        s0 += __shfl_xor_sync(0xffffffffu, s0, 1);
        s0 += __shfl_xor_sync(0xffffffffu, s0, 2);
        s1 += __shfl_xor_sync(0xffffffffu, s1, 1);
        s1 += __shfl_xor_sync(0xffffffffu, s1, 2);
        l0 = l0*a0 + s0;
        l1 = l1*a1 + s1;

#pragma unroll
        for (int nb = 0; nb < 16; nb++) {
            o[nb][0] *= a0; o[nb][1] *= a0; o[nb][2] *= a1; o[nb][3] *= a1;
        }

        uint32_t pa[4][4];
#pragma unroll
        for (int kc2 = 0; kc2 < 4; kc2++) {
            pa[kc2][0] = packh2(c[2*kc2][0],   c[2*kc2][1]);
            pa[kc2][1] = packh2(c[2*kc2][2],   c[2*kc2][3]);
            pa[kc2][2] = packh2(c[2*kc2+1][0], c[2*kc2+1][1]);
            pa[kc2][3] = packh2(c[2*kc2+1][2], c[2*kc2+1][3]);
        }

        int vrow = (lane & 7) + ((lane >> 3) & 1)*8;
        int npl  = ((lane >> 4) & 1)*8;
#pragma unroll
        for (int kc2 = 0; kc2 < 4; kc2++) {
            int row = kc2*16 + vrow;
#pragma unroll
            for (int nbp = 0; nbp < 8; nbp++) {
                uint32_t bf[4];
                int n = nbp*16 + npl;
                uint32_t ad = vst + (n>>6)*8192 + SMEM_SWIZZLE_128B((uint32_t)(row*128 + (n&63)*2));
                ldsm4t(bf, ad);
                mma16816(o[nbp*2],   pa[kc2], bf);
                mma16816(o[nbp*2+1], pa[kc2], bf + 2);
            }
        }
        __syncthreads();
    }

    float inv0 = 1.f / l0, inv1 = 1.f / l1;
    int r0 = q0 + wid*16 + (lane >> 2);
#pragma unroll
    for (int nb = 0; nb < 16; nb++) {
        int n = h*DH + nb*8 + (lane & 3)*2;
        if (mode == 0) {
            float* p0 = O + (size_t)r0*HD + n;
            float* p1 = O + (size_t)(r0+8)*HD + n;
            p0[0] = o[nb][0]*inv0; p0[1] = o[nb][1]*inv0;
            p1[0] = o[nb][2]*inv1; p1[1] = o[nb][3]*inv1;
        } else {
            const float* a0p = attn_in + (size_t)r0*HD + n;
            const float* a1p = attn_in + (size_t)(r0+8)*HD + n;
            __half* c0 = cat + (size_t)r0*CATN + n;
            __half* c1 = cat + (size_t)(r0+8)*CATN + n;
            c0[0] = __float2half_rn(a0p[0] + o[nb][0]*inv0);
            c0[1] = __float2half_rn(a0p[1] + o[nb][1]*inv0);
            c1[0] = __float2half_rn(a1p[0] + o[nb][2]*inv1);
            c1[1] = __float2half_rn(a1p[1] + o[nb][3]*inv1);
        }
    }
}

// ---------------- launcher ----------------
extern "C" void kernel_launch(void* const* d_in, const int* in_sizes, int n_in,
                              void* d_out, int out_size) {
    const float* x          = (const float*)d_in[0];
    const float* vec        = (const float*)d_in[1];
    const float* cosT       = (const float*)d_in[2];
    const float* sinT       = (const float*)d_in[3];
    const float* ref_latent = (const float*)d_in[4];
    const float* ref_cos    = (const float*)d_in[5];
    const float* ref_sin    = (const float*)d_in[6];
    const float* w_mod      = (const float*)d_in[7];
    const float* b_mod      = (const float*)d_in[8];
    const float* w1         = (const float*)d_in[9];
    const float* b1         = (const float*)d_in[10];
    const float* w2         = (const float*)d_in[11];
    const float* b2         = (const float*)d_in[12];
    const float* qn_w       = (const float*)d_in[13];
    const float* kn_w       = (const float*)d_in[14];
    const float* wk_ip      = (const float*)d_in[15];
    const float* bk_ip      = (const float*)d_in[16];
    const float* wv_ip      = (const float*)d_in[17];
    const float* bv_ip      = (const float*)d_in[18];
    const float* ref_kn_w   = (const float*)d_in[19];
    float* out = (float*)d_out;

    float *sv, *modb, *lin1, *attn, *refk, *refv;
    __half *xb, *cat, *rlb, *qb, *kb, *vb, *refkb, *refvb;
    __half *w1b, *w2b, *wkb, *wvb;
    cudaGetSymbolAddress((void**)&sv,     g_sv);
    cudaGetSymbolAddress((void**)&modb,   g_mod);
    cudaGetSymbolAddress((void**)&xb,     g_xb);
    cudaGetSymbolAddress((void**)&lin1,   g_lin1);
    cudaGetSymbolAddress((void**)&qb,     g_qb);
    cudaGetSymbolAddress((void**)&kb,     g_kb);
    cudaGetSymbolAddress((void**)&vb,     g_vb);
    cudaGetSymbolAddress((void**)&attn,   g_attn);
    cudaGetSymbolAddress((void**)&cat,    g_cat);
    cudaGetSymbolAddress((void**)&refk,   g_refk);
    cudaGetSymbolAddress((void**)&refv,   g_refv);
    cudaGetSymbolAddress((void**)&refkb,  g_refkb);
    cudaGetSymbolAddress((void**)&refvb,  g_refvb);
    cudaGetSymbolAddress((void**)&rlb,    g_rlb);
    cudaGetSymbolAddress((void**)&w1b,    g_w1b);
    cudaGetSymbolAddress((void**)&w2b,    g_w2b);
    cudaGetSymbolAddress((void**)&wkb,    g_wkb);
    cudaGetSymbolAddress((void**)&wvb,    g_wvb);

    cudaFuncSetAttribute(tc_gemm_kernel,
                         cudaFuncAttributeMaxDynamicSharedMemorySize, GK_SMEM_TOTAL);
    cudaFuncSetAttribute(fa_hmma_kernel,
                         cudaFuncAttributeMaxDynamicSharedMemorySize, FAH_SMEM);

    // lazily-created side streams/events (host resources, created once on the
    // uncaptured correctness call; reused identically under graph capture)
    static cudaStream_t s1 = nullptr, s2 = nullptr;
    static cudaEvent_t evRoot = nullptr, evW1 = nullptr, evRef = nullptr, evW2 = nullptr;
    if (!s1) {
        cudaStreamCreateWithFlags(&s1, cudaStreamNonBlocking);
        cudaStreamCreateWithFlags(&s2, cudaStreamNonBlocking);
        cudaEventCreateWithFlags(&evRoot, cudaEventDisableTiming);
        cudaEventCreateWithFlags(&evW1,   cudaEventDisableTiming);
        cudaEventCreateWithFlags(&evRef,  cudaEventDisableTiming);
        cudaEventCreateWithFlags(&evW2,   cudaEventDisableTiming);
    }

    dim3 tb(32, 8);

    // fork
    cudaEventRecord(evRoot, 0);
    cudaStreamWaitEvent(s1, evRoot, 0);
    cudaStreamWaitEvent(s2, evRoot, 0);

    // s1: w1 convert (feeds lin1 GEMM)
    wcvtT_kernel<<<dim3(L1N/32, HIDN/64), tb, 0, s1>>>(w1, w1b, HIDN, L1N);
    cudaEventRecord(evW1, s1);

    // s2: ref chain + w2 convert
    wcvtT_kernel<<<dim3(HIDN/32, HIDN/64), tb, 0, s2>>>(wk_ip, wkb, HIDN, HIDN);
    wcvtT_kernel<<<dim3(HIDN/32, HIDN/64), tb, 0, s2>>>(wv_ip, wvb, HIDN, HIDN);
    cvt_h_kernel<<<(REFN*HIDN + 255)/256, 256, 0, s2>>>(ref_latent, rlb, (size_t)REFN*HIDN);
    tc_gemm_kernel<<<(REFN/128)*(HIDN/128), 256, GK_SMEM_TOTAL, s2>>>(
        rlb, wkb, bk_ip, refk, nullptr, nullptr, nullptr, REFN, HIDN, HIDN, REFN/128, 0);
    tc_gemm_kernel<<<(REFN/128)*(HIDN/128), 256, GK_SMEM_TOTAL, s2>>>(
        rlb, wvb, bv_ip, refv, nullptr, nullptr, nullptr, REFN, HIDN, HIDN, REFN/128, 0);
    ref_norm_rope_kernel<<<dim3(REFN, NH), 128, 0, s2>>>(refk, ref_kn_w, ref_cos, ref_sin, refkb);
    cvt_h_kernel<<<(REFN*HIDN + 255)/256, 256, 0, s2>>>(refv, refvb, (size_t)REFN*HIDN);
    cudaEventRecord(evRef, s2);
    wcvtT_kernel<<<dim3(HIDN/32, CATN/64), tb, 0, s2>>>(w2, w2b, CATN, HIDN);
    cudaEventRecord(evW2, s2);

    // main stream: mod chain
    silu_kernel<<<12, 256>>>(vec, sv);
    modproj_kernel<<<(3*HIDN)/32, 256>>>(sv, w_mod, b_mod, modb);
    ln_mod_kernel<<<LTOT, 256>>>(x, modb, xb);

    // lin1 GEMM (gelu fused for mlp cols)
    cudaStreamWaitEvent(0, evW1, 0);
    tc_gemm_kernel<<<(LTOT/128)*(L1N/128), 256, GK_SMEM_TOTAL>>>(
        xb, w1b, b1, lin1, cat, nullptr, nullptr, LTOT, L1N, HIDN, LTOT/128, 1);

    // qkv norm/rope
    qkv_norm_rope_kernel<<<dim3(LTOT, NH), 128>>>(lin1, qn_w, kn_w, cosT, sinT, qb, kb, vb);

    // self-attention -> fp32 attn
    fa_hmma_kernel<<<dim3(LTOT/128, NH), 256, FAH_SMEM>>>(
        qb, kb, vb, attn, nullptr, nullptr, LTOT, 0);

    // IP attention: add + write fp16 cat
    cudaStreamWaitEvent(0, evRef, 0);
    fa_hmma_kernel<<<dim3(LTOT/128, NH), 256, FAH_SMEM>>>(
        qb, refkb, refvb, nullptr, attn, cat, REFN, 1);

    // out GEMM with fused gated residual
    cudaStreamWaitEvent(0, evW2, 0);
    tc_gemm_kernel<<<(LTOT/128)*(HIDN/128), 256, GK_SMEM_TOTAL>>>(
        cat, w2b, b2, out, nullptr, x, modb + 2*HIDN, LTOT, HIDN, CATN, LTOT/128, 2);
}